// round 11
// baseline (speedup 1.0000x reference)
#include <cuda_runtime.h>
#include <cstdint>

#define N_NODES 50000
#define N_EDGES 800000
#define IN_F 256
#define HID 128
#define OUT_F 64

#define SCAN_B 512
#define SCAN_NBLK ((N_NODES + SCAN_B - 1) / SCAN_B)   // 98

// packed fp32x2 FMA: d = a*b + d (elementwise on two packed floats)
#define FMA2(d, a, b) \
    asm("fma.rn.f32x2 %0, %1, %2, %0;" : "+l"(d) : "l"(a), "l"(b))

__device__ __forceinline__ float fx_lo(unsigned long long u) {
    return __uint_as_float((unsigned)u);
}
__device__ __forceinline__ float fx_hi(unsigned long long u) {
    return __uint_as_float((unsigned)(u >> 32));
}

// ---------------- scratch (device globals; no allocs allowed) ----------------
__device__ __align__(16) float g_m1[(size_t)N_NODES * HID];    // (x*ns) @ W1
__device__ __align__(16) float g_agg1[(size_t)N_NODES * HID];  // gather accum, layer 1
__device__ __align__(16) float g_m2[(size_t)N_NODES * OUT_F];  // (h*ns) @ W2
__device__ float g_ns[N_NODES];                  // deg_out^-1/2 (clamped)
__device__ float g_nd[N_NODES];                  // deg_in^-1/2 (clamped)
__device__ int   g_degs[N_NODES];                // out-degree (src)
__device__ int   g_degd[N_NODES];                // in-degree (dst)
__device__ int   g_rowptr[N_NODES + 1];          // CSR by dst
__device__ int   g_cur[N_NODES];                 // fill cursors
__device__ int   g_esrc[N_EDGES];                // src id per bucketed edge
__device__ int   g_src[N_EDGES];                 // normalized (int, clamped) src
__device__ int   g_dst[N_EDGES];                 // normalized (int, clamped) dst
__device__ int   g_bsum[SCAN_NBLK];
__device__ int   g_is32;                         // 1 if index arrays are int32

// ---------------- init ------------------------------------------------------
__global__ void k_init() {
    int i = blockIdx.x * blockDim.x + threadIdx.x;
    if (i < N_NODES) { g_degs[i] = 0; g_degd[i] = 0; }
    if (i == 0) g_is32 = 0;
}

// ---------------- dtype detect: int32 vs int64 indices -----------------------
__global__ void k_detect(const int* __restrict__ sw, const int* __restrict__ dw) {
    int t = blockIdx.x * 256 + threadIdx.x;
    int v = 0;
    if (t < N_EDGES / 2) v = sw[2 * t + 1] | dw[2 * t + 1];
    unsigned any = __ballot_sync(0xffffffffu, v != 0);
    if ((threadIdx.x & 31) == 0 && any) atomicOr(&g_is32, 1);
}

// ---------------- normalize indices + count degrees (fused) ------------------
__global__ void k_cvtdeg(const void* __restrict__ srcp, const void* __restrict__ dstp) {
    int e = blockIdx.x * 256 + threadIdx.x;
    if (e >= N_EDGES) return;
    int s, d;
    if (g_is32) {
        s = ((const int*)srcp)[e];
        d = ((const int*)dstp)[e];
    } else {
        s = (int)((const long long*)srcp)[e];
        d = (int)((const long long*)dstp)[e];
    }
    s = min(max(s, 0), N_NODES - 1);
    d = min(max(d, 0), N_NODES - 1);
    g_src[e] = s;
    g_dst[e] = d;
    atomicAdd(&g_degs[s], 1);
    atomicAdd(&g_degd[d], 1);
}

// ---------------- scan pass 1: block-local exclusive scan + norms ------------
__global__ void k_scan1() {
    __shared__ int sh[SCAN_B];
    int i = blockIdx.x * SCAN_B + threadIdx.x;
    int v = (i < N_NODES) ? g_degd[i] : 0;
    sh[threadIdx.x] = v;
    __syncthreads();
    #pragma unroll
    for (int off = 1; off < SCAN_B; off <<= 1) {
        int t = (threadIdx.x >= off) ? sh[threadIdx.x - off] : 0;
        __syncthreads();
        sh[threadIdx.x] += t;
        __syncthreads();
    }
    if (i < N_NODES) {
        g_rowptr[i] = sh[threadIdx.x] - v;   // exclusive
        int ds = g_degs[i]; if (ds < 1) ds = 1;
        int dd = v;         if (dd < 1) dd = 1;
        g_ns[i] = rsqrtf((float)ds);
        g_nd[i] = rsqrtf((float)dd);
    }
    if (threadIdx.x == SCAN_B - 1) g_bsum[blockIdx.x] = sh[threadIdx.x];
}

// ---------------- scan pass 2: per-block prefix of bsum + apply + cur=0 ------
__global__ void k_scan3() {
    __shared__ int warpsum[4];
    int t = threadIdx.x;
    int v = 0;
    if (t < 128) {
        if (t < SCAN_NBLK && t < (int)blockIdx.x) v = g_bsum[t];
        #pragma unroll
        for (int o = 16; o > 0; o >>= 1) v += __shfl_down_sync(0xffffffffu, v, o);
        if ((t & 31) == 0) warpsum[t >> 5] = v;
    }
    __syncthreads();
    int off = warpsum[0] + warpsum[1] + warpsum[2] + warpsum[3];
    int i = blockIdx.x * SCAN_B + t;
    if (i < N_NODES) { g_rowptr[i] += off; g_cur[i] = 0; }
    if (i == 0) g_rowptr[N_NODES] = N_EDGES;
}

// ---------------- bucket fill: edges grouped by dst --------------------------
__global__ void k_fill() {
    int e = blockIdx.x * blockDim.x + threadIdx.x;
    if (e >= N_EDGES) return;
    int d = g_dst[e];
    int pos = g_rowptr[d] + atomicAdd(&g_cur[d], 1);
    if (pos >= 0 && pos < N_EDGES) g_esrc[pos] = g_src[e];
}

// ---------------- GEMM1: m1 = (x .* ns) @ W1  (50000x256 @ 256x128) ----------
// 128x128 tile, 256 threads. f32x2 packed FMA: accumulators pair along M
// (natural pairs from [k][m] smem), B pre-duplicated {w,w} in smem with a
// group-interleaved layout (slot = off*16+g) for conflict-free LDS.128.
// Microtile: 8 m (4 pairs) x 8 j -> 32 fma2/k instead of 64 FFMA/k.
#define KC 16
__global__ void __launch_bounds__(256)
k_gemm1(const float* __restrict__ x, const float* __restrict__ W1) {
    __shared__ float  xs[KC][132];   // [k][m], padded
    __shared__ float4 ws2[KC][64];   // dup pairs: slot off*16+g holds j=8g+2*off,+1
    int t = threadIdx.x;
    int base = blockIdx.x * 128;
    int mg = t >> 4;          // 0..15
    int g  = t & 15;          // 0..15, owns j = g*8 .. g*8+7
    int m0 = mg * 8;
    unsigned long long acc[4][8] = {};   // [m-pair][jj], zero = {0.f,0.f}

    for (int k0 = 0; k0 < IN_F; k0 += KC) {
        __syncthreads();
        // ws2 fill: coalesced W1 float4 reads -> duplicated interleaved slots
        #pragma unroll
        for (int f = t; f < 512; f += 256) {
            int kk = f >> 5;
            int qq = f & 31;                 // float4 index within row (j0 = qq*4)
            float4 w = *(const float4*)(W1 + (k0 + kk) * HID + qq * 4);
            int gg  = qq >> 1;
            int off = (qq & 1) * 2;
            ws2[kk][off * 16 + gg]       = make_float4(w.x, w.x, w.y, w.y);
            ws2[kk][(off + 1) * 16 + gg] = make_float4(w.z, w.z, w.w, w.w);
        }
        // xs fill: x rows scaled by ns, transposed to [k][m]
        #pragma unroll
        for (int f = t; f < 512; f += 256) {
            int mm = f >> 2;
            int k4 = (f & 3) * 4;
            int node = base + mm; if (node >= N_NODES) node = N_NODES - 1;
            float ns = g_ns[node];
            float4 v = *(const float4*)(x + (size_t)node * IN_F + k0 + k4);
            xs[k4 + 0][mm] = v.x * ns;
            xs[k4 + 1][mm] = v.y * ns;
            xs[k4 + 2][mm] = v.z * ns;
            xs[k4 + 3][mm] = v.w * ns;
        }
        __syncthreads();
        #pragma unroll
        for (int k = 0; k < KC; k++) {
            ulonglong2 A0 = *(const ulonglong2*)&xs[k][m0];
            ulonglong2 A1 = *(const ulonglong2*)&xs[k][m0 + 4];
            unsigned long long pa0 = A0.x, pa1 = A0.y, pa2 = A1.x, pa3 = A1.y;
            #pragma unroll
            for (int q = 0; q < 4; q++) {
                ulonglong2 B = *(const ulonglong2*)&ws2[k][q * 16 + g];
                FMA2(acc[0][2 * q],     pa0, B.x);
                FMA2(acc[1][2 * q],     pa1, B.x);
                FMA2(acc[2][2 * q],     pa2, B.x);
                FMA2(acc[3][2 * q],     pa3, B.x);
                FMA2(acc[0][2 * q + 1], pa0, B.y);
                FMA2(acc[1][2 * q + 1], pa1, B.y);
                FMA2(acc[2][2 * q + 1], pa2, B.y);
                FMA2(acc[3][2 * q + 1], pa3, B.y);
            }
        }
    }
    // epilogue: low half = even row, high half = odd row
    #pragma unroll
    for (int ip = 0; ip < 4; ip++) {
        int me = base + m0 + 2 * ip;
        if (me < N_NODES) {
            float4 v0 = make_float4(fx_lo(acc[ip][0]), fx_lo(acc[ip][1]),
                                    fx_lo(acc[ip][2]), fx_lo(acc[ip][3]));
            float4 v1 = make_float4(fx_lo(acc[ip][4]), fx_lo(acc[ip][5]),
                                    fx_lo(acc[ip][6]), fx_lo(acc[ip][7]));
            *(float4*)(g_m1 + (size_t)me * HID + g * 8)     = v0;
            *(float4*)(g_m1 + (size_t)me * HID + g * 8 + 4) = v1;
        }
        if (me + 1 < N_NODES) {
            float4 v0 = make_float4(fx_hi(acc[ip][0]), fx_hi(acc[ip][1]),
                                    fx_hi(acc[ip][2]), fx_hi(acc[ip][3]));
            float4 v1 = make_float4(fx_hi(acc[ip][4]), fx_hi(acc[ip][5]),
                                    fx_hi(acc[ip][6]), fx_hi(acc[ip][7]));
            *(float4*)(g_m1 + (size_t)(me + 1) * HID + g * 8)     = v0;
            *(float4*)(g_m1 + (size_t)(me + 1) * HID + g * 8 + 4) = v1;
        }
    }
}

// ---------------- agg1: gather-sum m1 rows per dst (CSR) ---------------------
__global__ void __launch_bounds__(256)
k_agg1() {
    int n = (blockIdx.x * 256 + threadIdx.x) >> 5;
    if (n >= N_NODES) return;
    int l = threadIdx.x & 31;
    int s0 = g_rowptr[n];
    int e1 = g_rowptr[n + 1];
    float4 acc = make_float4(0.f, 0.f, 0.f, 0.f);
    int e = s0;
    for (; e + 3 < e1; e += 4) {
        int sa = g_esrc[e];
        int sb = g_esrc[e + 1];
        int sc = g_esrc[e + 2];
        int sd = g_esrc[e + 3];
        float4 va = ((const float4*)(g_m1 + (size_t)sa * HID))[l];
        float4 vb = ((const float4*)(g_m1 + (size_t)sb * HID))[l];
        float4 vc = ((const float4*)(g_m1 + (size_t)sc * HID))[l];
        float4 vd = ((const float4*)(g_m1 + (size_t)sd * HID))[l];
        acc.x += (va.x + vb.x) + (vc.x + vd.x);
        acc.y += (va.y + vb.y) + (vc.y + vd.y);
        acc.z += (va.z + vb.z) + (vc.z + vd.z);
        acc.w += (va.w + vb.w) + (vc.w + vd.w);
    }
    for (; e < e1; e++) {
        int sa = g_esrc[e];
        float4 va = ((const float4*)(g_m1 + (size_t)sa * HID))[l];
        acc.x += va.x; acc.y += va.y; acc.z += va.z; acc.w += va.w;
    }
    ((float4*)(g_agg1 + (size_t)n * HID))[l] = acc;
}

// ---------------- GEMM2: m2 = (relu(agg1*nd + b1) .* ns) @ W2  (128 -> 64) ---
// Same f32x2 scheme: 128x64 tile, 256 threads, microtile 4m(2 pairs) x 8j,
// K=128 in KC=16 chunks. Fused relu/bias/nd/ns in the hs tile load.
__global__ void __launch_bounds__(256)
k_gemm2(const float* __restrict__ b1, const float* __restrict__ W2) {
    __shared__ float  hs[KC][132];
    __shared__ float4 ws2[KC][32];   // slot off*8+g holds j=8g+2*off,+1 duplicated
    int t = threadIdx.x;
    int base = blockIdx.x * 128;
    int mg = t >> 3;          // 0..31
    int g  = t & 7;           // 0..7, owns j = g*8 .. g*8+7
    int m0 = mg * 4;
    unsigned long long acc[2][8] = {};

    for (int k0 = 0; k0 < HID; k0 += KC) {
        __syncthreads();
        // ws2 fill: 256 float4 of the W2 chunk, one per thread
        {
            int kk = t >> 4;
            int qq = t & 15;
            float4 w = *(const float4*)(W2 + (k0 + kk) * OUT_F + qq * 4);
            int gg  = qq >> 1;
            int off = (qq & 1) * 2;
            ws2[kk][off * 8 + gg]       = make_float4(w.x, w.x, w.y, w.y);
            ws2[kk][(off + 1) * 8 + gg] = make_float4(w.z, w.z, w.w, w.w);
        }
        // hs fill: fused relu(agg1*nd + b1)*ns, transposed to [k][m]
        float4 bv = *(const float4*)(b1 + k0 + ((t & 3) * 4));
        #pragma unroll
        for (int f = t; f < 512; f += 256) {
            int n  = f >> 2;
            int k4 = (f & 3) * 4;
            int node = base + n; if (node >= N_NODES) node = N_NODES - 1;
            float nd = g_nd[node];
            float ns = g_ns[node];
            float4 v = *(const float4*)(g_agg1 + (size_t)node * HID + k0 + k4);
            hs[k4 + 0][n] = fmaxf(v.x * nd + bv.x, 0.f) * ns;
            hs[k4 + 1][n] = fmaxf(v.y * nd + bv.y, 0.f) * ns;
            hs[k4 + 2][n] = fmaxf(v.z * nd + bv.z, 0.f) * ns;
            hs[k4 + 3][n] = fmaxf(v.w * nd + bv.w, 0.f) * ns;
        }
        __syncthreads();
        #pragma unroll
        for (int k = 0; k < KC; k++) {
            ulonglong2 A = *(const ulonglong2*)&hs[k][m0];
            unsigned long long pa0 = A.x, pa1 = A.y;
            #pragma unroll
            for (int q = 0; q < 4; q++) {
                ulonglong2 B = *(const ulonglong2*)&ws2[k][q * 8 + g];
                FMA2(acc[0][2 * q],     pa0, B.x);
                FMA2(acc[1][2 * q],     pa1, B.x);
                FMA2(acc[0][2 * q + 1], pa0, B.y);
                FMA2(acc[1][2 * q + 1], pa1, B.y);
            }
        }
    }
    #pragma unroll
    for (int ip = 0; ip < 2; ip++) {
        int me = base + m0 + 2 * ip;
        if (me < N_NODES) {
            float4 v0 = make_float4(fx_lo(acc[ip][0]), fx_lo(acc[ip][1]),
                                    fx_lo(acc[ip][2]), fx_lo(acc[ip][3]));
            float4 v1 = make_float4(fx_lo(acc[ip][4]), fx_lo(acc[ip][5]),
                                    fx_lo(acc[ip][6]), fx_lo(acc[ip][7]));
            *(float4*)(g_m2 + (size_t)me * OUT_F + g * 8)     = v0;
            *(float4*)(g_m2 + (size_t)me * OUT_F + g * 8 + 4) = v1;
        }
        if (me + 1 < N_NODES) {
            float4 v0 = make_float4(fx_hi(acc[ip][0]), fx_hi(acc[ip][1]),
                                    fx_hi(acc[ip][2]), fx_hi(acc[ip][3]));
            float4 v1 = make_float4(fx_hi(acc[ip][4]), fx_hi(acc[ip][5]),
                                    fx_hi(acc[ip][6]), fx_hi(acc[ip][7]));
            *(float4*)(g_m2 + (size_t)(me + 1) * OUT_F + g * 8)     = v0;
            *(float4*)(g_m2 + (size_t)(me + 1) * OUT_F + g * 8 + 4) = v1;
        }
    }
}

// ---------------- agg2 + finalize: out = (gather-sum m2) * nd + b2 -----------
__global__ void __launch_bounds__(256)
k_agg2(float* __restrict__ out, const float* __restrict__ b2) {
    int n = (blockIdx.x * 256 + threadIdx.x) >> 5;
    if (n >= N_NODES) return;
    int l = threadIdx.x & 31;
    int s0 = g_rowptr[n];
    int e1 = g_rowptr[n + 1];
    float2 acc = make_float2(0.f, 0.f);
    int e = s0;
    for (; e + 3 < e1; e += 4) {
        int sa = g_esrc[e];
        int sb = g_esrc[e + 1];
        int sc = g_esrc[e + 2];
        int sd = g_esrc[e + 3];
        float2 va = ((const float2*)(g_m2 + (size_t)sa * OUT_F))[l];
        float2 vb = ((const float2*)(g_m2 + (size_t)sb * OUT_F))[l];
        float2 vc = ((const float2*)(g_m2 + (size_t)sc * OUT_F))[l];
        float2 vd = ((const float2*)(g_m2 + (size_t)sd * OUT_F))[l];
        acc.x += (va.x + vb.x) + (vc.x + vd.x);
        acc.y += (va.y + vb.y) + (vc.y + vd.y);
    }
    for (; e < e1; e++) {
        int sa = g_esrc[e];
        float2 va = ((const float2*)(g_m2 + (size_t)sa * OUT_F))[l];
        acc.x += va.x; acc.y += va.y;
    }
    float nd = g_nd[n];
    float2 bv = ((const float2*)b2)[l];
    float2 r;
    r.x = acc.x * nd + bv.x;
    r.y = acc.y * nd + bv.y;
    ((float2*)(out + (size_t)n * OUT_F))[l] = r;
}

// ---------------- launch -----------------------------------------------------
extern "C" void kernel_launch(void* const* d_in, const int* in_sizes, int n_in,
                              void* d_out, int out_size) {
    // Identify inputs by element count (robust to any metadata ordering).
    const float *x = 0, *W1 = 0, *b1 = 0, *W2 = 0, *b2 = 0;
    const void *srcp = 0, *dstp = 0;
    for (int i = 0; i < n_in; i++) {
        switch (in_sizes[i]) {
            case N_NODES * IN_F: x  = (const float*)d_in[i]; break;   // 12,800,000
            case IN_F * HID:     W1 = (const float*)d_in[i]; break;   // 32,768
            case HID * OUT_F:    W2 = (const float*)d_in[i]; break;   // 8,192
            case HID:            b1 = (const float*)d_in[i]; break;   // 128
            case OUT_F:          b2 = (const float*)d_in[i]; break;   // 64
            case N_EDGES:                                              // 800,000 (x2)
                if (!srcp) srcp = d_in[i]; else dstp = d_in[i];
                break;
            default: break;
        }
    }
    float* out = (float*)d_out;

    k_init<<<(N_NODES + 255) / 256, 256>>>();
    k_detect<<<(N_EDGES / 2 + 255) / 256, 256>>>((const int*)srcp, (const int*)dstp);
    k_cvtdeg<<<(N_EDGES + 255) / 256, 256>>>(srcp, dstp);
    k_scan1<<<SCAN_NBLK, SCAN_B>>>();
    k_scan3<<<SCAN_NBLK, SCAN_B>>>();
    k_fill<<<(N_EDGES + 255) / 256, 256>>>();
    k_gemm1<<<(N_NODES + 127) / 128, 256>>>(x, W1);
    k_agg1<<<(N_NODES * 32) / 256, 256>>>();
    k_gemm2<<<(N_NODES + 127) / 128, 256>>>(b1, W2);
    k_agg2<<<(N_NODES * 32) / 256, 256>>>(out, b2);
}

// round 12
// speedup vs baseline: 1.1394x; 1.1394x over previous
#include <cuda_runtime.h>
#include <cstdint>

#define N_NODES 50000
#define N_EDGES 800000
#define IN_F 256
#define HID 128
#define OUT_F 64

#define SCAN_B 512
#define SCAN_NBLK ((N_NODES + SCAN_B - 1) / SCAN_B)   // 98

// ---------------- scratch (device globals; no allocs allowed) ----------------
__device__ __align__(16) float g_m1[(size_t)N_NODES * HID];    // x @ W1 (unscaled)
__device__ __align__(16) float g_agg1[(size_t)N_NODES * HID];  // gather accum, layer 1
__device__ __align__(16) float g_m2[(size_t)N_NODES * OUT_F];  // (h*ns) @ W2
__device__ float g_ns[N_NODES];                  // deg_out^-1/2 (clamped)
__device__ float g_nd[N_NODES];                  // deg_in^-1/2 (clamped)
__device__ int   g_degs[N_NODES];                // out-degree (src)
__device__ int   g_degd[N_NODES];                // in-degree (dst)
__device__ int   g_rowptr[N_NODES + 1];          // CSR by dst
__device__ int   g_cur[N_NODES];                 // fill cursors
__device__ int   g_esrc[N_EDGES];                // src id per bucketed edge
__device__ int   g_src[N_EDGES];                 // normalized (int, clamped) src
__device__ int   g_dst[N_EDGES];                 // normalized (int, clamped) dst
__device__ int   g_bsum[SCAN_NBLK];
__device__ int   g_is32;                         // sticky: 1 if indices are int32
                                                 // (zero-init at load; atomicOr is
                                                 //  idempotent for fixed inputs)

// ---------------- init degrees + dtype detect (fused) ------------------------
// Reading the first N_EDGES int32 words is safe for BOTH dtypes. If the data
// is little-endian int64 with values < 2^31, every odd word is 0.
__global__ void k_initdetect(const int* __restrict__ sw, const int* __restrict__ dw) {
    int t = blockIdx.x * 256 + threadIdx.x;
    if (t < N_NODES) { g_degs[t] = 0; g_degd[t] = 0; }
    int v = 0;
    if (t < N_EDGES / 2) v = sw[2 * t + 1] | dw[2 * t + 1];
    unsigned any = __ballot_sync(0xffffffffu, v != 0);
    if ((threadIdx.x & 31) == 0 && any) atomicOr(&g_is32, 1);
}

// ---------------- normalize indices + count degrees (fused) ------------------
__global__ void k_cvtdeg(const void* __restrict__ srcp, const void* __restrict__ dstp) {
    int e = blockIdx.x * 256 + threadIdx.x;
    if (e >= N_EDGES) return;
    int s, d;
    if (g_is32) {
        s = ((const int*)srcp)[e];
        d = ((const int*)dstp)[e];
    } else {
        s = (int)((const long long*)srcp)[e];
        d = (int)((const long long*)dstp)[e];
    }
    s = min(max(s, 0), N_NODES - 1);
    d = min(max(d, 0), N_NODES - 1);
    g_src[e] = s;
    g_dst[e] = d;
    atomicAdd(&g_degs[s], 1);
    atomicAdd(&g_degd[d], 1);
}

// ---------------- scan pass 1: block-local exclusive scan + norms ------------
__global__ void k_scan1() {
    __shared__ int sh[SCAN_B];
    int i = blockIdx.x * SCAN_B + threadIdx.x;
    int v = (i < N_NODES) ? g_degd[i] : 0;
    sh[threadIdx.x] = v;
    __syncthreads();
    #pragma unroll
    for (int off = 1; off < SCAN_B; off <<= 1) {
        int t = (threadIdx.x >= off) ? sh[threadIdx.x - off] : 0;
        __syncthreads();
        sh[threadIdx.x] += t;
        __syncthreads();
    }
    if (i < N_NODES) {
        g_rowptr[i] = sh[threadIdx.x] - v;   // exclusive
        int ds = g_degs[i]; if (ds < 1) ds = 1;
        int dd = v;         if (dd < 1) dd = 1;
        g_ns[i] = rsqrtf((float)ds);
        g_nd[i] = rsqrtf((float)dd);
    }
    if (threadIdx.x == SCAN_B - 1) g_bsum[blockIdx.x] = sh[threadIdx.x];
}

// ---------------- scan pass 2: per-block prefix of bsum + apply + cur=0 ------
__global__ void k_scan3() {
    __shared__ int warpsum[4];
    int t = threadIdx.x;
    int v = 0;
    if (t < 128) {
        if (t < SCAN_NBLK && t < (int)blockIdx.x) v = g_bsum[t];
        #pragma unroll
        for (int o = 16; o > 0; o >>= 1) v += __shfl_down_sync(0xffffffffu, v, o);
        if ((t & 31) == 0) warpsum[t >> 5] = v;
    }
    __syncthreads();
    int off = warpsum[0] + warpsum[1] + warpsum[2] + warpsum[3];
    int i = blockIdx.x * SCAN_B + t;
    if (i < N_NODES) { g_rowptr[i] += off; g_cur[i] = 0; }
    if (i == 0) g_rowptr[N_NODES] = N_EDGES;
}

// ---------------- bucket fill: edges grouped by dst --------------------------
__global__ void k_fill() {
    int e = blockIdx.x * blockDim.x + threadIdx.x;
    if (e >= N_EDGES) return;
    int d = g_dst[e];
    int pos = g_rowptr[d] + atomicAdd(&g_cur[d], 1);
    if (pos >= 0 && pos < N_EDGES) g_esrc[pos] = g_src[e];
}

// ---------------- GEMM1: m1 = x @ W1  (50000x256 @ 256x128), NO ns scaling ---
// (ns applied during agg1 gather -> gemm1 has no dependency on the CSR chain
//  and runs on a forked stream, overlapped with it.)
// Classic tiled SGEMM: 128x128 tile, 256 threads, 8x8 microtile, KC=16.
#define KC 16
__global__ void __launch_bounds__(256)
k_gemm1(const float* __restrict__ x, const float* __restrict__ W1) {
    __shared__ float xs[KC][132];   // [k][m], padded to dodge STS conflicts
    __shared__ float ws[KC][128];   // [k][n]
    int t = threadIdx.x;
    int base = blockIdx.x * 128;
    int m0 = (t >> 4) * 8;
    int n0 = (t & 15) * 8;
    float acc[8][8] = {};

    for (int k0 = 0; k0 < IN_F; k0 += KC) {
        __syncthreads();
        #pragma unroll
        for (int f = t; f < 512; f += 256) {
            int kk = f >> 5;
            int nn = (f & 31) * 4;
            *(float4*)(&ws[kk][nn]) = *(const float4*)(W1 + (k0 + kk) * HID + nn);
        }
        #pragma unroll
        for (int f = t; f < 512; f += 256) {
            int mm = f >> 2;
            int k4 = (f & 3) * 4;
            int node = base + mm; if (node >= N_NODES) node = N_NODES - 1;
            float4 v = *(const float4*)(x + (size_t)node * IN_F + k0 + k4);
            xs[k4 + 0][mm] = v.x;
            xs[k4 + 1][mm] = v.y;
            xs[k4 + 2][mm] = v.z;
            xs[k4 + 3][mm] = v.w;
        }
        __syncthreads();
        #pragma unroll
        for (int k = 0; k < KC; k++) {
            float a[8], b[8];
            *(float4*)(a)     = *(float4*)(&xs[k][m0]);
            *(float4*)(a + 4) = *(float4*)(&xs[k][m0 + 4]);
            *(float4*)(b)     = *(float4*)(&ws[k][n0]);
            *(float4*)(b + 4) = *(float4*)(&ws[k][n0 + 4]);
            #pragma unroll
            for (int i = 0; i < 8; i++)
                #pragma unroll
                for (int j = 0; j < 8; j++)
                    acc[i][j] += a[i] * b[j];
        }
    }
    #pragma unroll
    for (int i = 0; i < 8; i++) {
        int node = base + m0 + i;
        if (node < N_NODES) {
            *(float4*)(g_m1 + (size_t)node * HID + n0)     = *(float4*)(&acc[i][0]);
            *(float4*)(g_m1 + (size_t)node * HID + n0 + 4) = *(float4*)(&acc[i][4]);
        }
    }
}

// ---------------- agg1: agg1[n] = sum_{e in CSR[n]} ns[src] * m1[src] --------
// one warp per node; lane l owns float4 l of the 128-float row; 4-edge unroll.
// ns[src] scaling folded into the gather (broadcast load + FMA, issue-free).
__global__ void __launch_bounds__(256)
k_agg1() {
    int n = (blockIdx.x * 256 + threadIdx.x) >> 5;
    if (n >= N_NODES) return;
    int l = threadIdx.x & 31;
    int s0 = g_rowptr[n];
    int e1 = g_rowptr[n + 1];
    float4 acc = make_float4(0.f, 0.f, 0.f, 0.f);
    int e = s0;
    for (; e + 3 < e1; e += 4) {
        int sa = g_esrc[e];
        int sb = g_esrc[e + 1];
        int sc = g_esrc[e + 2];
        int sd = g_esrc[e + 3];
        float na = g_ns[sa], nb = g_ns[sb], nc = g_ns[sc], ne = g_ns[sd];
        float4 va = ((const float4*)(g_m1 + (size_t)sa * HID))[l];
        float4 vb = ((const float4*)(g_m1 + (size_t)sb * HID))[l];
        float4 vc = ((const float4*)(g_m1 + (size_t)sc * HID))[l];
        float4 vd = ((const float4*)(g_m1 + (size_t)sd * HID))[l];
        acc.x += (na * va.x + nb * vb.x) + (nc * vc.x + ne * vd.x);
        acc.y += (na * va.y + nb * vb.y) + (nc * vc.y + ne * vd.y);
        acc.z += (na * va.z + nb * vb.z) + (nc * vc.z + ne * vd.z);
        acc.w += (na * va.w + nb * vb.w) + (nc * vc.w + ne * vd.w);
    }
    for (; e < e1; e++) {
        int sa = g_esrc[e];
        float na = g_ns[sa];
        float4 va = ((const float4*)(g_m1 + (size_t)sa * HID))[l];
        acc.x += na * va.x; acc.y += na * va.y;
        acc.z += na * va.z; acc.w += na * va.w;
    }
    ((float4*)(g_agg1 + (size_t)n * HID))[l] = acc;
}

// ---------------- GEMM2: m2 = (relu(agg1*nd + b1) .* ns) @ W2  (128 -> 64) ---
__global__ void __launch_bounds__(256)
k_gemm2(const float* __restrict__ b1, const float* __restrict__ W2) {
    __shared__ float sW[HID * OUT_F];  // 32KB
    __shared__ float sh[16 * HID];     // 8KB
    int t = threadIdx.x;

    float4* sW4 = (float4*)sW;
    const float4* W24 = (const float4*)W2;
    for (int i = t; i < HID * OUT_F / 4; i += 256) sW4[i] = W24[i];

    int j  = t & (OUT_F - 1);
    int ng = t >> 6;  // 0..3

    for (int tile = blockIdx.x; tile < N_NODES / 16; tile += gridDim.x) {
        int base = tile * 16;
        __syncthreads();
        for (int i = t; i < 16 * HID / 4; i += 256) {
            int n = i >> 5;
            int kk = i & 31;
            int node = base + n;
            float nd = g_nd[node];
            float ns = g_ns[node];
            float4 v  = ((const float4*)(g_agg1 + (size_t)node * HID))[kk];
            float4 bv = ((const float4*)b1)[kk];
            float4 h;
            h.x = fmaxf(v.x * nd + bv.x, 0.f) * ns;
            h.y = fmaxf(v.y * nd + bv.y, 0.f) * ns;
            h.z = fmaxf(v.z * nd + bv.z, 0.f) * ns;
            h.w = fmaxf(v.w * nd + bv.w, 0.f) * ns;
            ((float4*)(sh + n * HID))[kk] = h;
        }
        __syncthreads();

        const float* h0 = sh + (ng * 4 + 0) * HID;
        const float* h1 = sh + (ng * 4 + 1) * HID;
        const float* h2 = sh + (ng * 4 + 2) * HID;
        const float* h3 = sh + (ng * 4 + 3) * HID;
        float acc0 = 0.f, acc1 = 0.f, acc2 = 0.f, acc3 = 0.f;
        #pragma unroll 8
        for (int k = 0; k < HID; k += 4) {
            float4 a0 = *(const float4*)(h0 + k);
            float4 a1 = *(const float4*)(h1 + k);
            float4 a2 = *(const float4*)(h2 + k);
            float4 a3 = *(const float4*)(h3 + k);
            float w0 = sW[(k + 0) * OUT_F + j];
            float w1 = sW[(k + 1) * OUT_F + j];
            float w2 = sW[(k + 2) * OUT_F + j];
            float w3 = sW[(k + 3) * OUT_F + j];
            acc0 += a0.x * w0 + a0.y * w1 + a0.z * w2 + a0.w * w3;
            acc1 += a1.x * w0 + a1.y * w1 + a1.z * w2 + a1.w * w3;
            acc2 += a2.x * w0 + a2.y * w1 + a2.z * w2 + a2.w * w3;
            acc3 += a3.x * w0 + a3.y * w1 + a3.z * w2 + a3.w * w3;
        }
        int nb = base + ng * 4;
        g_m2[(size_t)(nb + 0) * OUT_F + j] = acc0;
        g_m2[(size_t)(nb + 1) * OUT_F + j] = acc1;
        g_m2[(size_t)(nb + 2) * OUT_F + j] = acc2;
        g_m2[(size_t)(nb + 3) * OUT_F + j] = acc3;
    }
}

// ---------------- agg2 + finalize: out = (gather-sum m2) * nd + b2 -----------
__global__ void __launch_bounds__(256)
k_agg2(float* __restrict__ out, const float* __restrict__ b2) {
    int n = (blockIdx.x * 256 + threadIdx.x) >> 5;
    if (n >= N_NODES) return;
    int l = threadIdx.x & 31;
    int s0 = g_rowptr[n];
    int e1 = g_rowptr[n + 1];
    float2 acc = make_float2(0.f, 0.f);
    int e = s0;
    for (; e + 3 < e1; e += 4) {
        int sa = g_esrc[e];
        int sb = g_esrc[e + 1];
        int sc = g_esrc[e + 2];
        int sd = g_esrc[e + 3];
        float2 va = ((const float2*)(g_m2 + (size_t)sa * OUT_F))[l];
        float2 vb = ((const float2*)(g_m2 + (size_t)sb * OUT_F))[l];
        float2 vc = ((const float2*)(g_m2 + (size_t)sc * OUT_F))[l];
        float2 vd = ((const float2*)(g_m2 + (size_t)sd * OUT_F))[l];
        acc.x += (va.x + vb.x) + (vc.x + vd.x);
        acc.y += (va.y + vb.y) + (vc.y + vd.y);
    }
    for (; e < e1; e++) {
        int sa = g_esrc[e];
        float2 va = ((const float2*)(g_m2 + (size_t)sa * OUT_F))[l];
        acc.x += va.x; acc.y += va.y;
    }
    float nd = g_nd[n];
    float2 bv = ((const float2*)b2)[l];
    float2 r;
    r.x = acc.x * nd + bv.x;
    r.y = acc.y * nd + bv.y;
    ((float2*)(out + (size_t)n * OUT_F))[l] = r;
}

// ---------------- launch -----------------------------------------------------
extern "C" void kernel_launch(void* const* d_in, const int* in_sizes, int n_in,
                              void* d_out, int out_size) {
    // Identify inputs by element count (robust to any metadata ordering).
    const float *x = 0, *W1 = 0, *b1 = 0, *W2 = 0, *b2 = 0;
    const void *srcp = 0, *dstp = 0;
    for (int i = 0; i < n_in; i++) {
        switch (in_sizes[i]) {
            case N_NODES * IN_F: x  = (const float*)d_in[i]; break;   // 12,800,000
            case IN_F * HID:     W1 = (const float*)d_in[i]; break;   // 32,768
            case HID * OUT_F:    W2 = (const float*)d_in[i]; break;   // 8,192
            case HID:            b1 = (const float*)d_in[i]; break;   // 128
            case OUT_F:          b2 = (const float*)d_in[i]; break;   // 64
            case N_EDGES:                                              // 800,000 (x2)
                if (!srcp) srcp = d_in[i]; else dstp = d_in[i];
                break;
            default: break;
        }
    }
    float* out = (float*)d_out;

    // One-time side-stream + events (host objects only; created outside capture
    // on the harness's eager correctness call, reused during capture/replay).
    static cudaStream_t s2 = 0;
    static cudaEvent_t evFork = 0, evJoin = 0;
    if (!s2) {
        cudaStreamCreateWithFlags(&s2, cudaStreamNonBlocking);
        cudaEventCreateWithFlags(&evFork, cudaEventDisableTiming);
        cudaEventCreateWithFlags(&evJoin, cudaEventDisableTiming);
    }

    // Fork: gemm1 (x @ W1, no CSR dependency) overlaps the whole CSR build.
    cudaEventRecord(evFork, 0);
    cudaStreamWaitEvent(s2, evFork, 0);
    k_gemm1<<<(N_NODES + 127) / 128, 256, 0, s2>>>(x, W1);
    cudaEventRecord(evJoin, s2);

    // Main stream: CSR build chain.
    k_initdetect<<<(N_EDGES / 2 + 255) / 256, 256>>>((const int*)srcp, (const int*)dstp);
    k_cvtdeg<<<(N_EDGES + 255) / 256, 256>>>(srcp, dstp);
    k_scan1<<<SCAN_NBLK, SCAN_B>>>();
    k_scan3<<<SCAN_NBLK, SCAN_B>>>();
    k_fill<<<(N_EDGES + 255) / 256, 256>>>();

    // Join: agg1 needs both m1 (s2) and the CSR (main).
    cudaStreamWaitEvent(0, evJoin, 0);
    k_agg1<<<(N_NODES * 32) / 256, 256>>>();
    k_gemm2<<<592, 256>>>(b1, W2);
    k_agg2<<<(N_NODES * 32) / 256, 256>>>(out, b2);
}

// round 13
// speedup vs baseline: 1.3816x; 1.2125x over previous
#include <cuda_runtime.h>
#include <cstdint>

#define N_NODES 50000
#define N_EDGES 800000
#define IN_F 256
#define HID 128
#define OUT_F 64

#define SCAN_B 512
#define SCAN_NBLK ((N_NODES + SCAN_B - 1) / SCAN_B)   // 98

// ---------------- scratch (device globals; no allocs allowed) ----------------
__device__ __align__(16) float g_m1[(size_t)N_NODES * HID];    // x @ W1 (unscaled)
__device__ __align__(16) float g_agg1[(size_t)N_NODES * HID];  // gather accum, layer 1
__device__ __align__(16) float g_m2[(size_t)N_NODES * OUT_F];  // (h*ns) @ W2
__device__ float g_ns[N_NODES];                  // deg_out^-1/2 (clamped)
__device__ float g_nd[N_NODES];                  // deg_in^-1/2 (clamped)
__device__ int   g_degs[N_NODES];                // out-degree (src)
__device__ int   g_degd[N_NODES];                // in-degree (dst)
__device__ int   g_rowptr[N_NODES + 1];          // CSR by dst
__device__ int   g_cur[N_NODES];                 // fill cursors
__device__ int   g_esrc[N_EDGES];                // src id per bucketed edge
__device__ int   g_src[N_EDGES];                 // normalized (int, clamped) src
__device__ int   g_dst[N_EDGES];                 // normalized (int, clamped) dst
__device__ int   g_bsum[SCAN_NBLK];
__device__ int   g_is32;                         // sticky: 1 if indices are int32

// ---------------- tf32 helpers ----------------------------------------------
__device__ __forceinline__ unsigned f2tf32(float f) {
    unsigned r;
    asm("cvt.rna.tf32.f32 %0, %1;" : "=r"(r) : "f"(f));
    return r;
}
__device__ __forceinline__ void mma_tf32(float* d, const unsigned* a,
                                         unsigned b0, unsigned b1) {
    asm("mma.sync.aligned.m16n8k8.row.col.f32.tf32.tf32.f32 "
        "{%0,%1,%2,%3}, {%4,%5,%6,%7}, {%8,%9}, {%0,%1,%2,%3};"
        : "+f"(d[0]), "+f"(d[1]), "+f"(d[2]), "+f"(d[3])
        : "r"(a[0]), "r"(a[1]), "r"(a[2]), "r"(a[3]), "r"(b0), "r"(b1));
}

// ---------------- init degrees + dtype detect (fused) ------------------------
__global__ void k_initdetect(const int* __restrict__ sw, const int* __restrict__ dw) {
    int t = blockIdx.x * 256 + threadIdx.x;
    if (t < N_NODES) { g_degs[t] = 0; g_degd[t] = 0; }
    int v = 0;
    if (t < N_EDGES / 2) v = sw[2 * t + 1] | dw[2 * t + 1];
    unsigned any = __ballot_sync(0xffffffffu, v != 0);
    if ((threadIdx.x & 31) == 0 && any) atomicOr(&g_is32, 1);
}

// ---------------- normalize indices + count degrees (fused) ------------------
__global__ void k_cvtdeg(const void* __restrict__ srcp, const void* __restrict__ dstp) {
    int e = blockIdx.x * 256 + threadIdx.x;
    if (e >= N_EDGES) return;
    int s, d;
    if (g_is32) {
        s = ((const int*)srcp)[e];
        d = ((const int*)dstp)[e];
    } else {
        s = (int)((const long long*)srcp)[e];
        d = (int)((const long long*)dstp)[e];
    }
    s = min(max(s, 0), N_NODES - 1);
    d = min(max(d, 0), N_NODES - 1);
    g_src[e] = s;
    g_dst[e] = d;
    atomicAdd(&g_degs[s], 1);
    atomicAdd(&g_degd[d], 1);
}

// ---------------- scan pass 1: block-local exclusive scan + norms ------------
__global__ void k_scan1() {
    __shared__ int sh[SCAN_B];
    int i = blockIdx.x * SCAN_B + threadIdx.x;
    int v = (i < N_NODES) ? g_degd[i] : 0;
    sh[threadIdx.x] = v;
    __syncthreads();
    #pragma unroll
    for (int off = 1; off < SCAN_B; off <<= 1) {
        int t = (threadIdx.x >= off) ? sh[threadIdx.x - off] : 0;
        __syncthreads();
        sh[threadIdx.x] += t;
        __syncthreads();
    }
    if (i < N_NODES) {
        g_rowptr[i] = sh[threadIdx.x] - v;   // exclusive
        int ds = g_degs[i]; if (ds < 1) ds = 1;
        int dd = v;         if (dd < 1) dd = 1;
        g_ns[i] = rsqrtf((float)ds);
        g_nd[i] = rsqrtf((float)dd);
    }
    if (threadIdx.x == SCAN_B - 1) g_bsum[blockIdx.x] = sh[threadIdx.x];
}

// ---------------- scan pass 2: per-block prefix of bsum + apply + cur=0 ------
__global__ void k_scan3() {
    __shared__ int warpsum[4];
    int t = threadIdx.x;
    int v = 0;
    if (t < 128) {
        if (t < SCAN_NBLK && t < (int)blockIdx.x) v = g_bsum[t];
        #pragma unroll
        for (int o = 16; o > 0; o >>= 1) v += __shfl_down_sync(0xffffffffu, v, o);
        if ((t & 31) == 0) warpsum[t >> 5] = v;
    }
    __syncthreads();
    int off = warpsum[0] + warpsum[1] + warpsum[2] + warpsum[3];
    int i = blockIdx.x * SCAN_B + t;
    if (i < N_NODES) { g_rowptr[i] += off; g_cur[i] = 0; }
    if (i == 0) g_rowptr[N_NODES] = N_EDGES;
}

// ---------------- bucket fill: edges grouped by dst --------------------------
__global__ void k_fill() {
    int e = blockIdx.x * blockDim.x + threadIdx.x;
    if (e >= N_EDGES) return;
    int d = g_dst[e];
    int pos = g_rowptr[d] + atomicAdd(&g_cur[d], 1);
    if (pos >= 0 && pos < N_EDGES) g_esrc[pos] = g_src[e];
}

// ---------------- GEMM1 (tf32 tensor cores): m1 = x @ W1 ---------------------
// 128x128 tile, 256 threads (8 warps), warp owns 16 rows x 128 cols.
// mma.sync m16n8k8 tf32; K chunked by 32. smem padded to 136 cols so the
// fragment LDS pattern (bank = 8*tig + g) is conflict-free.
// ns scaling deferred to agg1 -> no CSR dependency; runs on forked stream.
#define KCH 32
__global__ void __launch_bounds__(256)
k_gemm1(const float* __restrict__ x, const float* __restrict__ W1) {
    __shared__ unsigned xs[KCH][136];   // tf32 bits, [k][m]
    __shared__ unsigned ws[KCH][136];   // tf32 bits, [k][n]
    int t = threadIdx.x;
    int base = blockIdx.x * 128;
    int warp = t >> 5;
    int lane = t & 31;
    int g   = lane >> 2;    // 0..7
    int tig = lane & 3;     // 0..3
    int mw  = warp * 16;

    float acc[16][4];
    #pragma unroll
    for (int nt = 0; nt < 16; nt++)
        #pragma unroll
        for (int i = 0; i < 4; i++) acc[nt][i] = 0.f;

    for (int k0 = 0; k0 < IN_F; k0 += KCH) {
        __syncthreads();
        // ws fill: W1 chunk [KCH][128] -> tf32 (already [k][n])
        #pragma unroll
        for (int f = t; f < 1024; f += 256) {
            int kk = f >> 5;
            int nn = (f & 31) * 4;
            float4 w = *(const float4*)(W1 + (k0 + kk) * HID + nn);
            ws[kk][nn + 0] = f2tf32(w.x);
            ws[kk][nn + 1] = f2tf32(w.y);
            ws[kk][nn + 2] = f2tf32(w.z);
            ws[kk][nn + 3] = f2tf32(w.w);
        }
        // xs fill: x rows -> tf32, transposed to [k][m]
        #pragma unroll
        for (int f = t; f < 1024; f += 256) {
            int mm = f >> 3;
            int k4 = (f & 7) * 4;
            int node = base + mm; if (node >= N_NODES) node = N_NODES - 1;
            float4 v = *(const float4*)(x + (size_t)node * IN_F + k0 + k4);
            xs[k4 + 0][mm] = f2tf32(v.x);
            xs[k4 + 1][mm] = f2tf32(v.y);
            xs[k4 + 2][mm] = f2tf32(v.z);
            xs[k4 + 3][mm] = f2tf32(v.w);
        }
        __syncthreads();
        #pragma unroll
        for (int ks = 0; ks < KCH / 8; ks++) {
            int kb = ks * 8;
            unsigned a[4];
            a[0] = xs[kb + tig][mw + g];          // A[m=mw+g   ][k=kb+tig  ]
            a[1] = xs[kb + tig][mw + g + 8];      // A[m=mw+g+8 ][k=kb+tig  ]
            a[2] = xs[kb + tig + 4][mw + g];      // A[m=mw+g   ][k=kb+tig+4]
            a[3] = xs[kb + tig + 4][mw + g + 8];  // A[m=mw+g+8 ][k=kb+tig+4]
            #pragma unroll
            for (int nt = 0; nt < 16; nt++) {
                unsigned b0 = ws[kb + tig][nt * 8 + g];      // B[k=tig  ][n=g]
                unsigned b1 = ws[kb + tig + 4][nt * 8 + g];  // B[k=tig+4][n=g]
                mma_tf32(acc[nt], a, b0, b1);
            }
        }
    }
    // epilogue: c0,c1 -> row g, cols tig*2,+1 ; c2,c3 -> row g+8
    int r0 = base + mw + g;
    int r1 = r0 + 8;
    #pragma unroll
    for (int nt = 0; nt < 16; nt++) {
        int c = nt * 8 + tig * 2;
        if (r0 < N_NODES)
            *(float2*)(g_m1 + (size_t)r0 * HID + c) = make_float2(acc[nt][0], acc[nt][1]);
        if (r1 < N_NODES)
            *(float2*)(g_m1 + (size_t)r1 * HID + c) = make_float2(acc[nt][2], acc[nt][3]);
    }
}

// ---------------- agg1: agg1[n] = sum_{e in CSR[n]} ns[src] * m1[src] --------
__global__ void __launch_bounds__(256)
k_agg1() {
    int n = (blockIdx.x * 256 + threadIdx.x) >> 5;
    if (n >= N_NODES) return;
    int l = threadIdx.x & 31;
    int s0 = g_rowptr[n];
    int e1 = g_rowptr[n + 1];
    float4 acc = make_float4(0.f, 0.f, 0.f, 0.f);
    int e = s0;
    for (; e + 3 < e1; e += 4) {
        int sa = g_esrc[e];
        int sb = g_esrc[e + 1];
        int sc = g_esrc[e + 2];
        int sd = g_esrc[e + 3];
        float na = g_ns[sa], nb = g_ns[sb], nc = g_ns[sc], ne = g_ns[sd];
        float4 va = ((const float4*)(g_m1 + (size_t)sa * HID))[l];
        float4 vb = ((const float4*)(g_m1 + (size_t)sb * HID))[l];
        float4 vc = ((const float4*)(g_m1 + (size_t)sc * HID))[l];
        float4 vd = ((const float4*)(g_m1 + (size_t)sd * HID))[l];
        acc.x += (na * va.x + nb * vb.x) + (nc * vc.x + ne * vd.x);
        acc.y += (na * va.y + nb * vb.y) + (nc * vc.y + ne * vd.y);
        acc.z += (na * va.z + nb * vb.z) + (nc * vc.z + ne * vd.z);
        acc.w += (na * va.w + nb * vb.w) + (nc * vc.w + ne * vd.w);
    }
    for (; e < e1; e++) {
        int sa = g_esrc[e];
        float na = g_ns[sa];
        float4 va = ((const float4*)(g_m1 + (size_t)sa * HID))[l];
        acc.x += na * va.x; acc.y += na * va.y;
        acc.z += na * va.z; acc.w += na * va.w;
    }
    ((float4*)(g_agg1 + (size_t)n * HID))[l] = acc;
}

// ---------------- GEMM2: m2 = (relu(agg1*nd + b1) .* ns) @ W2  (128 -> 64) ---
__global__ void __launch_bounds__(256)
k_gemm2(const float* __restrict__ b1, const float* __restrict__ W2) {
    __shared__ float sW[HID * OUT_F];  // 32KB
    __shared__ float sh[16 * HID];     // 8KB
    int t = threadIdx.x;

    float4* sW4 = (float4*)sW;
    const float4* W24 = (const float4*)W2;
    for (int i = t; i < HID * OUT_F / 4; i += 256) sW4[i] = W24[i];

    int j  = t & (OUT_F - 1);
    int ng = t >> 6;  // 0..3

    for (int tile = blockIdx.x; tile < N_NODES / 16; tile += gridDim.x) {
        int base = tile * 16;
        __syncthreads();
        for (int i = t; i < 16 * HID / 4; i += 256) {
            int n = i >> 5;
            int kk = i & 31;
            int node = base + n;
            float nd = g_nd[node];
            float ns = g_ns[node];
            float4 v  = ((const float4*)(g_agg1 + (size_t)node * HID))[kk];
            float4 bv = ((const float4*)b1)[kk];
            float4 h;
            h.x = fmaxf(v.x * nd + bv.x, 0.f) * ns;
            h.y = fmaxf(v.y * nd + bv.y, 0.f) * ns;
            h.z = fmaxf(v.z * nd + bv.z, 0.f) * ns;
            h.w = fmaxf(v.w * nd + bv.w, 0.f) * ns;
            ((float4*)(sh + n * HID))[kk] = h;
        }
        __syncthreads();

        const float* h0 = sh + (ng * 4 + 0) * HID;
        const float* h1 = sh + (ng * 4 + 1) * HID;
        const float* h2 = sh + (ng * 4 + 2) * HID;
        const float* h3 = sh + (ng * 4 + 3) * HID;
        float acc0 = 0.f, acc1 = 0.f, acc2 = 0.f, acc3 = 0.f;
        #pragma unroll 8
        for (int k = 0; k < HID; k += 4) {
            float4 a0 = *(const float4*)(h0 + k);
            float4 a1 = *(const float4*)(h1 + k);
            float4 a2 = *(const float4*)(h2 + k);
            float4 a3 = *(const float4*)(h3 + k);
            float w0 = sW[(k + 0) * OUT_F + j];
            float w1 = sW[(k + 1) * OUT_F + j];
            float w2 = sW[(k + 2) * OUT_F + j];
            float w3 = sW[(k + 3) * OUT_F + j];
            acc0 += a0.x * w0 + a0.y * w1 + a0.z * w2 + a0.w * w3;
            acc1 += a1.x * w0 + a1.y * w1 + a1.z * w2 + a1.w * w3;
            acc2 += a2.x * w0 + a2.y * w1 + a2.z * w2 + a2.w * w3;
            acc3 += a3.x * w0 + a3.y * w1 + a3.z * w2 + a3.w * w3;
        }
        int nb = base + ng * 4;
        g_m2[(size_t)(nb + 0) * OUT_F + j] = acc0;
        g_m2[(size_t)(nb + 1) * OUT_F + j] = acc1;
        g_m2[(size_t)(nb + 2) * OUT_F + j] = acc2;
        g_m2[(size_t)(nb + 3) * OUT_F + j] = acc3;
    }
}

// ---------------- agg2 + finalize: out = (gather-sum m2) * nd + b2 -----------
__global__ void __launch_bounds__(256)
k_agg2(float* __restrict__ out, const float* __restrict__ b2) {
    int n = (blockIdx.x * 256 + threadIdx.x) >> 5;
    if (n >= N_NODES) return;
    int l = threadIdx.x & 31;
    int s0 = g_rowptr[n];
    int e1 = g_rowptr[n + 1];
    float2 acc = make_float2(0.f, 0.f);
    int e = s0;
    for (; e + 3 < e1; e += 4) {
        int sa = g_esrc[e];
        int sb = g_esrc[e + 1];
        int sc = g_esrc[e + 2];
        int sd = g_esrc[e + 3];
        float2 va = ((const float2*)(g_m2 + (size_t)sa * OUT_F))[l];
        float2 vb = ((const float2*)(g_m2 + (size_t)sb * OUT_F))[l];
        float2 vc = ((const float2*)(g_m2 + (size_t)sc * OUT_F))[l];
        float2 vd = ((const float2*)(g_m2 + (size_t)sd * OUT_F))[l];
        acc.x += (va.x + vb.x) + (vc.x + vd.x);
        acc.y += (va.y + vb.y) + (vc.y + vd.y);
    }
    for (; e < e1; e++) {
        int sa = g_esrc[e];
        float2 va = ((const float2*)(g_m2 + (size_t)sa * OUT_F))[l];
        acc.x += va.x; acc.y += va.y;
    }
    float nd = g_nd[n];
    float2 bv = ((const float2*)b2)[l];
    float2 r;
    r.x = acc.x * nd + bv.x;
    r.y = acc.y * nd + bv.y;
    ((float2*)(out + (size_t)n * OUT_F))[l] = r;
}

// ---------------- launch -----------------------------------------------------
extern "C" void kernel_launch(void* const* d_in, const int* in_sizes, int n_in,
                              void* d_out, int out_size) {
    // Identify inputs by element count (robust to any metadata ordering).
    const float *x = 0, *W1 = 0, *b1 = 0, *W2 = 0, *b2 = 0;
    const void *srcp = 0, *dstp = 0;
    for (int i = 0; i < n_in; i++) {
        switch (in_sizes[i]) {
            case N_NODES * IN_F: x  = (const float*)d_in[i]; break;   // 12,800,000
            case IN_F * HID:     W1 = (const float*)d_in[i]; break;   // 32,768
            case HID * OUT_F:    W2 = (const float*)d_in[i]; break;   // 8,192
            case HID:            b1 = (const float*)d_in[i]; break;   // 128
            case OUT_F:          b2 = (const float*)d_in[i]; break;   // 64
            case N_EDGES:                                              // 800,000 (x2)
                if (!srcp) srcp = d_in[i]; else dstp = d_in[i];
                break;
            default: break;
        }
    }
    float* out = (float*)d_out;

    // One-time side-stream + events (host objects only; created outside capture
    // on the harness's eager correctness call, reused during capture/replay).
    static cudaStream_t s2 = 0;
    static cudaEvent_t evFork = 0, evJoin = 0;
    if (!s2) {
        cudaStreamCreateWithFlags(&s2, cudaStreamNonBlocking);
        cudaEventCreateWithFlags(&evFork, cudaEventDisableTiming);
        cudaEventCreateWithFlags(&evJoin, cudaEventDisableTiming);
    }

    // Fork: gemm1 (x @ W1, no CSR dependency) overlaps the whole CSR build.
    cudaEventRecord(evFork, 0);
    cudaStreamWaitEvent(s2, evFork, 0);
    k_gemm1<<<(N_NODES + 127) / 128, 256, 0, s2>>>(x, W1);
    cudaEventRecord(evJoin, s2);

    // Main stream: CSR build chain.
    k_initdetect<<<(N_EDGES / 2 + 255) / 256, 256>>>((const int*)srcp, (const int*)dstp);
    k_cvtdeg<<<(N_EDGES + 255) / 256, 256>>>(srcp, dstp);
    k_scan1<<<SCAN_NBLK, SCAN_B>>>();
    k_scan3<<<SCAN_NBLK, SCAN_B>>>();
    k_fill<<<(N_EDGES + 255) / 256, 256>>>();

    // Join: agg1 needs both m1 (s2) and the CSR (main).
    cudaStreamWaitEvent(0, evJoin, 0);
    k_agg1<<<(N_NODES * 32) / 256, 256>>>();
    k_gemm2<<<592, 256>>>(b1, W2);
    k_agg2<<<(N_NODES * 32) / 256, 256>>>(out, b2);
}

// round 14
// speedup vs baseline: 1.7050x; 1.2341x over previous
#include <cuda_runtime.h>
#include <cstdint>

#define N_NODES 50000
#define N_EDGES 800000
#define IN_F 256
#define HID 128
#define OUT_F 64

#define SCAN_B 512
#define SCAN_NBLK ((N_NODES + SCAN_B - 1) / SCAN_B)   // 98

// ---------------- scratch (device globals; no allocs allowed) ----------------
__device__ __align__(16) float g_m1[(size_t)N_NODES * HID];    // x @ W1 (unscaled)
__device__ __align__(16) float g_agg1[(size_t)N_NODES * HID];  // gather accum, layer 1
__device__ __align__(16) float g_m2[(size_t)N_NODES * OUT_F];  // (h*ns) @ W2
__device__ float g_ns[N_NODES];                  // deg_out^-1/2 (clamped)
__device__ float g_nd[N_NODES];                  // deg_in^-1/2 (clamped)
__device__ int   g_degs[N_NODES];                // out-degree (src)
__device__ int   g_degd[N_NODES];                // in-degree (dst)
__device__ int   g_rowptr[N_NODES + 1];          // CSR by dst
__device__ int   g_cur[N_NODES];                 // fill cursors
__device__ int   g_esrc[N_EDGES];                // src id per bucketed edge
__device__ int   g_src[N_EDGES];                 // normalized (int, clamped) src
__device__ int   g_dst[N_EDGES];                 // normalized (int, clamped) dst
__device__ int   g_bsum[SCAN_NBLK];
__device__ int   g_is32;                         // sticky: 1 if indices are int32

// ---------------- tf32 helpers ----------------------------------------------
__device__ __forceinline__ unsigned f2tf32(float f) {
    unsigned r;
    asm("cvt.rna.tf32.f32 %0, %1;" : "=r"(r) : "f"(f));
    return r;
}
__device__ __forceinline__ void mma_tf32(float* d, const unsigned* a,
                                         unsigned b0, unsigned b1) {
    asm("mma.sync.aligned.m16n8k8.row.col.f32.tf32.tf32.f32 "
        "{%0,%1,%2,%3}, {%4,%5,%6,%7}, {%8,%9}, {%0,%1,%2,%3};"
        : "+f"(d[0]), "+f"(d[1]), "+f"(d[2]), "+f"(d[3])
        : "r"(a[0]), "r"(a[1]), "r"(a[2]), "r"(a[3]), "r"(b0), "r"(b1));
}

// ---------------- init degrees + dtype detect (fused) ------------------------
__global__ void k_initdetect(const int* __restrict__ sw, const int* __restrict__ dw) {
    int t = blockIdx.x * 256 + threadIdx.x;
    if (t < N_NODES) { g_degs[t] = 0; g_degd[t] = 0; }
    int v = 0;
    if (t < N_EDGES / 2) v = sw[2 * t + 1] | dw[2 * t + 1];
    unsigned any = __ballot_sync(0xffffffffu, v != 0);
    if ((threadIdx.x & 31) == 0 && any) atomicOr(&g_is32, 1);
}

// ---------------- normalize indices + count degrees (fused) ------------------
__global__ void k_cvtdeg(const void* __restrict__ srcp, const void* __restrict__ dstp) {
    int e = blockIdx.x * 256 + threadIdx.x;
    if (e >= N_EDGES) return;
    int s, d;
    if (g_is32) {
        s = ((const int*)srcp)[e];
        d = ((const int*)dstp)[e];
    } else {
        s = (int)((const long long*)srcp)[e];
        d = (int)((const long long*)dstp)[e];
    }
    s = min(max(s, 0), N_NODES - 1);
    d = min(max(d, 0), N_NODES - 1);
    g_src[e] = s;
    g_dst[e] = d;
    atomicAdd(&g_degs[s], 1);
    atomicAdd(&g_degd[d], 1);
}

// ---------------- scan pass 1: shuffle-based block scan + norms --------------
__global__ void k_scan1() {
    __shared__ int wsum[16];
    int t = threadIdx.x;
    int lane = t & 31;
    int w = t >> 5;
    int i = blockIdx.x * SCAN_B + t;
    int v = (i < N_NODES) ? g_degd[i] : 0;
    // warp inclusive scan
    int sc = v;
    #pragma unroll
    for (int o = 1; o < 32; o <<= 1) {
        int u = __shfl_up_sync(0xffffffffu, sc, o);
        if (lane >= o) sc += u;
    }
    if (lane == 31) wsum[w] = sc;
    __syncthreads();
    if (w == 0) {
        int ws = (lane < 16) ? wsum[lane] : 0;
        #pragma unroll
        for (int o = 1; o < 16; o <<= 1) {
            int u = __shfl_up_sync(0xffffffffu, ws, o);
            if (lane >= o) ws += u;
        }
        if (lane < 16) wsum[lane] = ws;
    }
    __syncthreads();
    int incl = sc + (w > 0 ? wsum[w - 1] : 0);
    if (i < N_NODES) {
        g_rowptr[i] = incl - v;   // exclusive
        int ds = g_degs[i]; if (ds < 1) ds = 1;
        int dd = v;         if (dd < 1) dd = 1;
        g_ns[i] = rsqrtf((float)ds);
        g_nd[i] = rsqrtf((float)dd);
    }
    if (t == SCAN_B - 1) g_bsum[blockIdx.x] = incl;
}

// ---------------- scan pass 2: per-block prefix of bsum + apply + cur=0 ------
__global__ void k_scan3() {
    __shared__ int warpsum[4];
    int t = threadIdx.x;
    int v = 0;
    if (t < 128) {
        if (t < SCAN_NBLK && t < (int)blockIdx.x) v = g_bsum[t];
        #pragma unroll
        for (int o = 16; o > 0; o >>= 1) v += __shfl_down_sync(0xffffffffu, v, o);
        if ((t & 31) == 0) warpsum[t >> 5] = v;
    }
    __syncthreads();
    int off = warpsum[0] + warpsum[1] + warpsum[2] + warpsum[3];
    int i = blockIdx.x * SCAN_B + t;
    if (i < N_NODES) { g_rowptr[i] += off; g_cur[i] = 0; }
    if (i == 0) g_rowptr[N_NODES] = N_EDGES;
}

// ---------------- bucket fill: edges grouped by dst --------------------------
__global__ void k_fill() {
    int e = blockIdx.x * blockDim.x + threadIdx.x;
    if (e >= N_EDGES) return;
    int d = g_dst[e];
    int pos = g_rowptr[d] + atomicAdd(&g_cur[d], 1);
    if (pos >= 0 && pos < N_EDGES) g_esrc[pos] = g_src[e];
}

// ---------------- GEMM1 (tf32 tensor cores): m1 = x @ W1 ---------------------
// 128x128 tile, 256 threads (8 warps), warp owns 16 rows x 128 cols.
#define KCH 32
__global__ void __launch_bounds__(256)
k_gemm1(const float* __restrict__ x, const float* __restrict__ W1) {
    __shared__ unsigned xs[KCH][136];   // tf32 bits, [k][m]
    __shared__ unsigned ws[KCH][136];   // tf32 bits, [k][n]
    int t = threadIdx.x;
    int base = blockIdx.x * 128;
    int warp = t >> 5;
    int lane = t & 31;
    int g   = lane >> 2;    // 0..7
    int tig = lane & 3;     // 0..3
    int mw  = warp * 16;

    float acc[16][4];
    #pragma unroll
    for (int nt = 0; nt < 16; nt++)
        #pragma unroll
        for (int i = 0; i < 4; i++) acc[nt][i] = 0.f;

    for (int k0 = 0; k0 < IN_F; k0 += KCH) {
        __syncthreads();
        #pragma unroll
        for (int f = t; f < 1024; f += 256) {
            int kk = f >> 5;
            int nn = (f & 31) * 4;
            float4 w = *(const float4*)(W1 + (k0 + kk) * HID + nn);
            ws[kk][nn + 0] = f2tf32(w.x);
            ws[kk][nn + 1] = f2tf32(w.y);
            ws[kk][nn + 2] = f2tf32(w.z);
            ws[kk][nn + 3] = f2tf32(w.w);
        }
        #pragma unroll
        for (int f = t; f < 1024; f += 256) {
            int mm = f >> 3;
            int k4 = (f & 7) * 4;
            int node = base + mm; if (node >= N_NODES) node = N_NODES - 1;
            float4 v = *(const float4*)(x + (size_t)node * IN_F + k0 + k4);
            xs[k4 + 0][mm] = f2tf32(v.x);
            xs[k4 + 1][mm] = f2tf32(v.y);
            xs[k4 + 2][mm] = f2tf32(v.z);
            xs[k4 + 3][mm] = f2tf32(v.w);
        }
        __syncthreads();
        #pragma unroll
        for (int ks = 0; ks < KCH / 8; ks++) {
            int kb = ks * 8;
            unsigned a[4];
            a[0] = xs[kb + tig][mw + g];
            a[1] = xs[kb + tig][mw + g + 8];
            a[2] = xs[kb + tig + 4][mw + g];
            a[3] = xs[kb + tig + 4][mw + g + 8];
            #pragma unroll
            for (int nt = 0; nt < 16; nt++) {
                unsigned b0 = ws[kb + tig][nt * 8 + g];
                unsigned b1 = ws[kb + tig + 4][nt * 8 + g];
                mma_tf32(acc[nt], a, b0, b1);
            }
        }
    }
    int r0 = base + mw + g;
    int r1 = r0 + 8;
    #pragma unroll
    for (int nt = 0; nt < 16; nt++) {
        int c = nt * 8 + tig * 2;
        if (r0 < N_NODES)
            *(float2*)(g_m1 + (size_t)r0 * HID + c) = make_float2(acc[nt][0], acc[nt][1]);
        if (r1 < N_NODES)
            *(float2*)(g_m1 + (size_t)r1 * HID + c) = make_float2(acc[nt][2], acc[nt][3]);
    }
}

// ---------------- agg1: agg1[n] = sum_{e in CSR[n]} ns[src] * m1[src] --------
__global__ void __launch_bounds__(256)
k_agg1() {
    int n = (blockIdx.x * 256 + threadIdx.x) >> 5;
    if (n >= N_NODES) return;
    int l = threadIdx.x & 31;
    int s0 = g_rowptr[n];
    int e1 = g_rowptr[n + 1];
    float4 acc = make_float4(0.f, 0.f, 0.f, 0.f);
    int e = s0;
    for (; e + 3 < e1; e += 4) {
        int sa = g_esrc[e];
        int sb = g_esrc[e + 1];
        int sc = g_esrc[e + 2];
        int sd = g_esrc[e + 3];
        float na = g_ns[sa], nb = g_ns[sb], nc = g_ns[sc], ne = g_ns[sd];
        float4 va = ((const float4*)(g_m1 + (size_t)sa * HID))[l];
        float4 vb = ((const float4*)(g_m1 + (size_t)sb * HID))[l];
        float4 vc = ((const float4*)(g_m1 + (size_t)sc * HID))[l];
        float4 vd = ((const float4*)(g_m1 + (size_t)sd * HID))[l];
        acc.x += (na * va.x + nb * vb.x) + (nc * vc.x + ne * vd.x);
        acc.y += (na * va.y + nb * vb.y) + (nc * vc.y + ne * vd.y);
        acc.z += (na * va.z + nb * vb.z) + (nc * vc.z + ne * vd.z);
        acc.w += (na * va.w + nb * vb.w) + (nc * vc.w + ne * vd.w);
    }
    for (; e < e1; e++) {
        int sa = g_esrc[e];
        float na = g_ns[sa];
        float4 va = ((const float4*)(g_m1 + (size_t)sa * HID))[l];
        acc.x += na * va.x; acc.y += na * va.y;
        acc.z += na * va.z; acc.w += na * va.w;
    }
    ((float4*)(g_agg1 + (size_t)n * HID))[l] = acc;
}

// ---------------- GEMM2 (tf32 tensor cores): m2 = h @ W2 ---------------------
// h = relu(agg1*nd + b1) * ns, fused into the hs tile load.
// 128x64 tile, 256 threads (8 warps), warp owns 16 rows x 64 cols (8 n-tiles).
// K=128 in 4 chunks of 32. hs pad 136, ws pad 72 (both ≡ 8 mod 32 -> the
// fragment pattern bank = 8*tig + g + 8*nt is conflict-free).
__global__ void __launch_bounds__(256)
k_gemm2(const float* __restrict__ b1, const float* __restrict__ W2) {
    __shared__ unsigned hs[KCH][136];   // tf32 bits, [k][m]
    __shared__ unsigned ws[KCH][72];    // tf32 bits, [k][n]
    int t = threadIdx.x;
    int base = blockIdx.x * 128;
    int warp = t >> 5;
    int lane = t & 31;
    int g   = lane >> 2;
    int tig = lane & 3;
    int mw  = warp * 16;

    float acc[8][4];
    #pragma unroll
    for (int nt = 0; nt < 8; nt++)
        #pragma unroll
        for (int i = 0; i < 4; i++) acc[nt][i] = 0.f;

    for (int k0 = 0; k0 < HID; k0 += KCH) {
        __syncthreads();
        // ws fill: W2 chunk [KCH][64] -> tf32
        #pragma unroll
        for (int f = t; f < 512; f += 256) {
            int kk = f >> 4;
            int nn = (f & 15) * 4;
            float4 w = *(const float4*)(W2 + (k0 + kk) * OUT_F + nn);
            ws[kk][nn + 0] = f2tf32(w.x);
            ws[kk][nn + 1] = f2tf32(w.y);
            ws[kk][nn + 2] = f2tf32(w.z);
            ws[kk][nn + 3] = f2tf32(w.w);
        }
        // hs fill: fused relu(agg1*nd + b1)*ns -> tf32, transposed to [k][m]
        #pragma unroll
        for (int f = t; f < 1024; f += 256) {
            int mm = f >> 3;
            int k4 = (f & 7) * 4;
            int node = base + mm; if (node >= N_NODES) node = N_NODES - 1;
            float nd = g_nd[node];
            float ns = g_ns[node];
            float4 v  = *(const float4*)(g_agg1 + (size_t)node * HID + k0 + k4);
            float4 bv = *(const float4*)(b1 + k0 + k4);
            hs[k4 + 0][mm] = f2tf32(fmaxf(v.x * nd + bv.x, 0.f) * ns);
            hs[k4 + 1][mm] = f2tf32(fmaxf(v.y * nd + bv.y, 0.f) * ns);
            hs[k4 + 2][mm] = f2tf32(fmaxf(v.z * nd + bv.z, 0.f) * ns);
            hs[k4 + 3][mm] = f2tf32(fmaxf(v.w * nd + bv.w, 0.f) * ns);
        }
        __syncthreads();
        #pragma unroll
        for (int ks = 0; ks < KCH / 8; ks++) {
            int kb = ks * 8;
            unsigned a[4];
            a[0] = hs[kb + tig][mw + g];
            a[1] = hs[kb + tig][mw + g + 8];
            a[2] = hs[kb + tig + 4][mw + g];
            a[3] = hs[kb + tig + 4][mw + g + 8];
            #pragma unroll
            for (int nt = 0; nt < 8; nt++) {
                unsigned b0 = ws[kb + tig][nt * 8 + g];
                unsigned b1r = ws[kb + tig + 4][nt * 8 + g];
                mma_tf32(acc[nt], a, b0, b1r);
            }
        }
    }
    int r0 = base + mw + g;
    int r1 = r0 + 8;
    #pragma unroll
    for (int nt = 0; nt < 8; nt++) {
        int c = nt * 8 + tig * 2;
        if (r0 < N_NODES)
            *(float2*)(g_m2 + (size_t)r0 * OUT_F + c) = make_float2(acc[nt][0], acc[nt][1]);
        if (r1 < N_NODES)
            *(float2*)(g_m2 + (size_t)r1 * OUT_F + c) = make_float2(acc[nt][2], acc[nt][3]);
    }
}

// ---------------- agg2 + finalize: out = (gather-sum m2) * nd + b2 -----------
__global__ void __launch_bounds__(256)
k_agg2(float* __restrict__ out, const float* __restrict__ b2) {
    int n = (blockIdx.x * 256 + threadIdx.x) >> 5;
    if (n >= N_NODES) return;
    int l = threadIdx.x & 31;
    int s0 = g_rowptr[n];
    int e1 = g_rowptr[n + 1];
    float2 acc = make_float2(0.f, 0.f);
    int e = s0;
    for (; e + 3 < e1; e += 4) {
        int sa = g_esrc[e];
        int sb = g_esrc[e + 1];
        int sc = g_esrc[e + 2];
        int sd = g_esrc[e + 3];
        float2 va = ((const float2*)(g_m2 + (size_t)sa * OUT_F))[l];
        float2 vb = ((const float2*)(g_m2 + (size_t)sb * OUT_F))[l];
        float2 vc = ((const float2*)(g_m2 + (size_t)sc * OUT_F))[l];
        float2 vd = ((const float2*)(g_m2 + (size_t)sd * OUT_F))[l];
        acc.x += (va.x + vb.x) + (vc.x + vd.x);
        acc.y += (va.y + vb.y) + (vc.y + vd.y);
    }
    for (; e < e1; e++) {
        int sa = g_esrc[e];
        float2 va = ((const float2*)(g_m2 + (size_t)sa * OUT_F))[l];
        acc.x += va.x; acc.y += va.y;
    }
    float nd = g_nd[n];
    float2 bv = ((const float2*)b2)[l];
    float2 r;
    r.x = acc.x * nd + bv.x;
    r.y = acc.y * nd + bv.y;
    ((float2*)(out + (size_t)n * OUT_F))[l] = r;
}

// ---------------- launch -----------------------------------------------------
extern "C" void kernel_launch(void* const* d_in, const int* in_sizes, int n_in,
                              void* d_out, int out_size) {
    // Identify inputs by element count (robust to any metadata ordering).
    const float *x = 0, *W1 = 0, *b1 = 0, *W2 = 0, *b2 = 0;
    const void *srcp = 0, *dstp = 0;
    for (int i = 0; i < n_in; i++) {
        switch (in_sizes[i]) {
            case N_NODES * IN_F: x  = (const float*)d_in[i]; break;   // 12,800,000
            case IN_F * HID:     W1 = (const float*)d_in[i]; break;   // 32,768
            case HID * OUT_F:    W2 = (const float*)d_in[i]; break;   // 8,192
            case HID:            b1 = (const float*)d_in[i]; break;   // 128
            case OUT_F:          b2 = (const float*)d_in[i]; break;   // 64
            case N_EDGES:                                              // 800,000 (x2)
                if (!srcp) srcp = d_in[i]; else dstp = d_in[i];
                break;
            default: break;
        }
    }
    float* out = (float*)d_out;

    // One-time side-stream + events (host objects only; created outside capture
    // on the harness's eager correctness call, reused during capture/replay).
    static cudaStream_t s2 = 0;
    static cudaEvent_t evFork = 0, evJoin = 0;
    if (!s2) {
        cudaStreamCreateWithFlags(&s2, cudaStreamNonBlocking);
        cudaEventCreateWithFlags(&evFork, cudaEventDisableTiming);
        cudaEventCreateWithFlags(&evJoin, cudaEventDisableTiming);
    }

    // Fork: gemm1 (x @ W1, no CSR dependency) overlaps the whole CSR build.
    cudaEventRecord(evFork, 0);
    cudaStreamWaitEvent(s2, evFork, 0);
    k_gemm1<<<(N_NODES + 127) / 128, 256, 0, s2>>>(x, W1);
    cudaEventRecord(evJoin, s2);

    // Main stream: CSR build chain.
    k_initdetect<<<(N_EDGES / 2 + 255) / 256, 256>>>((const int*)srcp, (const int*)dstp);
    k_cvtdeg<<<(N_EDGES + 255) / 256, 256>>>(srcp, dstp);
    k_scan1<<<SCAN_NBLK, SCAN_B>>>();
    k_scan3<<<SCAN_NBLK, SCAN_B>>>();
    k_fill<<<(N_EDGES + 255) / 256, 256>>>();

    // Join: agg1 needs both m1 (s2) and the CSR (main).
    cudaStreamWaitEvent(0, evJoin, 0);
    k_agg1<<<(N_NODES * 32) / 256, 256>>>();
    k_gemm2<<<(N_NODES + 127) / 128, 256>>>(b1, W2);
    k_agg2<<<(N_NODES * 32) / 256, 256>>>(out, b2);
}

// round 15
// speedup vs baseline: 1.8030x; 1.0575x over previous
#include <cuda_runtime.h>
#include <cuda_fp16.h>
#include <cstdint>

#define N_NODES 50000
#define N_EDGES 800000
#define IN_F 256
#define HID 128
#define OUT_F 64

#define SCAN_B 512
#define SCAN_NBLK ((N_NODES + SCAN_B - 1) / SCAN_B)   // 98

// ---------------- scratch (device globals; no allocs allowed) ----------------
__device__ __align__(16) __half g_m1h[(size_t)N_NODES * HID];  // x @ W1, fp16
__device__ __align__(16) float g_agg1[(size_t)N_NODES * HID];  // gather accum, layer 1
__device__ __align__(16) float g_m2[(size_t)N_NODES * OUT_F];  // (h*ns) @ W2
__device__ float g_ns[N_NODES];                  // deg_out^-1/2 (clamped)
__device__ float g_nd[N_NODES];                  // deg_in^-1/2 (clamped)
__device__ int   g_degs[N_NODES];                // out-degree (src)
__device__ int   g_degd[N_NODES];                // in-degree (dst)
__device__ int   g_rowptr[N_NODES + 1];          // CSR by dst
__device__ int   g_esrc[N_EDGES];                // src id per bucketed edge
__device__ int   g_src[N_EDGES];                 // normalized (int, clamped) src
__device__ int   g_dst[N_EDGES];                 // normalized (int, clamped) dst
__device__ int   g_rank[N_EDGES];                // within-dst-bucket rank
__device__ int   g_bsum[SCAN_NBLK];
__device__ int   g_is32;                         // sticky: 1 if indices are int32

// ---------------- tf32 helpers ----------------------------------------------
__device__ __forceinline__ unsigned f2tf32(float f) {
    unsigned r;
    asm("cvt.rna.tf32.f32 %0, %1;" : "=r"(r) : "f"(f));
    return r;
}
__device__ __forceinline__ void mma_tf32(float* d, const unsigned* a,
                                         unsigned b0, unsigned b1) {
    asm("mma.sync.aligned.m16n8k8.row.col.f32.tf32.tf32.f32 "
        "{%0,%1,%2,%3}, {%4,%5,%6,%7}, {%8,%9}, {%0,%1,%2,%3};"
        : "+f"(d[0]), "+f"(d[1]), "+f"(d[2]), "+f"(d[3])
        : "r"(a[0]), "r"(a[1]), "r"(a[2]), "r"(a[3]), "r"(b0), "r"(b1));
}

// ---------------- init degrees + dtype detect (fused) ------------------------
__global__ void k_initdetect(const int* __restrict__ sw, const int* __restrict__ dw) {
    int t = blockIdx.x * 256 + threadIdx.x;
    if (t < N_NODES) { g_degs[t] = 0; g_degd[t] = 0; }
    int v = 0;
    if (t < N_EDGES / 2) v = sw[2 * t + 1] | dw[2 * t + 1];
    unsigned any = __ballot_sync(0xffffffffu, v != 0);
    if ((threadIdx.x & 31) == 0 && any) atomicOr(&g_is32, 1);
}

// ---------------- normalize indices + degrees + bucket rank (fused) ----------
// The atomicAdd on g_degd both counts the in-degree AND returns this edge's
// rank within its dst bucket -> k_fill needs no atomics at all.
__global__ void k_cvtdeg(const void* __restrict__ srcp, const void* __restrict__ dstp) {
    int e = blockIdx.x * 256 + threadIdx.x;
    if (e >= N_EDGES) return;
    int s, d;
    if (g_is32) {
        s = ((const int*)srcp)[e];
        d = ((const int*)dstp)[e];
    } else {
        s = (int)((const long long*)srcp)[e];
        d = (int)((const long long*)dstp)[e];
    }
    s = min(max(s, 0), N_NODES - 1);
    d = min(max(d, 0), N_NODES - 1);
    g_src[e] = s;
    g_dst[e] = d;
    atomicAdd(&g_degs[s], 1);
    g_rank[e] = atomicAdd(&g_degd[d], 1);
}

// ---------------- scan pass 1: shuffle-based block scan + norms --------------
__global__ void k_scan1() {
    __shared__ int wsum[16];
    int t = threadIdx.x;
    int lane = t & 31;
    int w = t >> 5;
    int i = blockIdx.x * SCAN_B + t;
    int v = (i < N_NODES) ? g_degd[i] : 0;
    int sc = v;
    #pragma unroll
    for (int o = 1; o < 32; o <<= 1) {
        int u = __shfl_up_sync(0xffffffffu, sc, o);
        if (lane >= o) sc += u;
    }
    if (lane == 31) wsum[w] = sc;
    __syncthreads();
    if (w == 0) {
        int ws = (lane < 16) ? wsum[lane] : 0;
        #pragma unroll
        for (int o = 1; o < 16; o <<= 1) {
            int u = __shfl_up_sync(0xffffffffu, ws, o);
            if (lane >= o) ws += u;
        }
        if (lane < 16) wsum[lane] = ws;
    }
    __syncthreads();
    int incl = sc + (w > 0 ? wsum[w - 1] : 0);
    if (i < N_NODES) {
        g_rowptr[i] = incl - v;   // exclusive
        int ds = g_degs[i]; if (ds < 1) ds = 1;
        int dd = v;         if (dd < 1) dd = 1;
        g_ns[i] = rsqrtf((float)ds);
        g_nd[i] = rsqrtf((float)dd);
    }
    if (t == SCAN_B - 1) g_bsum[blockIdx.x] = incl;
}

// ---------------- scan pass 2: per-block prefix of bsum + apply --------------
__global__ void k_scan3() {
    __shared__ int warpsum[4];
    int t = threadIdx.x;
    int v = 0;
    if (t < 128) {
        if (t < SCAN_NBLK && t < (int)blockIdx.x) v = g_bsum[t];
        #pragma unroll
        for (int o = 16; o > 0; o >>= 1) v += __shfl_down_sync(0xffffffffu, v, o);
        if ((t & 31) == 0) warpsum[t >> 5] = v;
    }
    __syncthreads();
    int off = warpsum[0] + warpsum[1] + warpsum[2] + warpsum[3];
    int i = blockIdx.x * SCAN_B + t;
    if (i < N_NODES) g_rowptr[i] += off;
    if (i == 0) g_rowptr[N_NODES] = N_EDGES;
}

// ---------------- bucket fill: atomic-free (rank precomputed) ----------------
__global__ void k_fill() {
    int e = blockIdx.x * blockDim.x + threadIdx.x;
    if (e >= N_EDGES) return;
    int d = g_dst[e];
    g_esrc[g_rowptr[d] + g_rank[e]] = g_src[e];
}

// ---------------- GEMM1 (tf32 tensor cores): m1 = x @ W1, fp16 out -----------
// 128x128 tile, 256 threads (8 warps), warp owns 16 rows x 128 cols.
#define KCH 32
__global__ void __launch_bounds__(256)
k_gemm1(const float* __restrict__ x, const float* __restrict__ W1) {
    __shared__ unsigned xs[KCH][136];   // tf32 bits, [k][m]
    __shared__ unsigned ws[KCH][136];   // tf32 bits, [k][n]
    int t = threadIdx.x;
    int base = blockIdx.x * 128;
    int warp = t >> 5;
    int lane = t & 31;
    int g   = lane >> 2;    // 0..7
    int tig = lane & 3;     // 0..3
    int mw  = warp * 16;

    float acc[16][4];
    #pragma unroll
    for (int nt = 0; nt < 16; nt++)
        #pragma unroll
        for (int i = 0; i < 4; i++) acc[nt][i] = 0.f;

    for (int k0 = 0; k0 < IN_F; k0 += KCH) {
        __syncthreads();
        #pragma unroll
        for (int f = t; f < 1024; f += 256) {
            int kk = f >> 5;
            int nn = (f & 31) * 4;
            float4 w = *(const float4*)(W1 + (k0 + kk) * HID + nn);
            ws[kk][nn + 0] = f2tf32(w.x);
            ws[kk][nn + 1] = f2tf32(w.y);
            ws[kk][nn + 2] = f2tf32(w.z);
            ws[kk][nn + 3] = f2tf32(w.w);
        }
        #pragma unroll
        for (int f = t; f < 1024; f += 256) {
            int mm = f >> 3;
            int k4 = (f & 7) * 4;
            int node = base + mm; if (node >= N_NODES) node = N_NODES - 1;
            float4 v = *(const float4*)(x + (size_t)node * IN_F + k0 + k4);
            xs[k4 + 0][mm] = f2tf32(v.x);
            xs[k4 + 1][mm] = f2tf32(v.y);
            xs[k4 + 2][mm] = f2tf32(v.z);
            xs[k4 + 3][mm] = f2tf32(v.w);
        }
        __syncthreads();
        #pragma unroll
        for (int ks = 0; ks < KCH / 8; ks++) {
            int kb = ks * 8;
            unsigned a[4];
            a[0] = xs[kb + tig][mw + g];
            a[1] = xs[kb + tig][mw + g + 8];
            a[2] = xs[kb + tig + 4][mw + g];
            a[3] = xs[kb + tig + 4][mw + g + 8];
            #pragma unroll
            for (int nt = 0; nt < 16; nt++) {
                unsigned b0 = ws[kb + tig][nt * 8 + g];
                unsigned b1 = ws[kb + tig + 4][nt * 8 + g];
                mma_tf32(acc[nt], a, b0, b1);
            }
        }
    }
    int r0 = base + mw + g;
    int r1 = r0 + 8;
    #pragma unroll
    for (int nt = 0; nt < 16; nt++) {
        int c = nt * 8 + tig * 2;
        if (r0 < N_NODES)
            *(__half2*)(g_m1h + (size_t)r0 * HID + c) =
                __floats2half2_rn(acc[nt][0], acc[nt][1]);
        if (r1 < N_NODES)
            *(__half2*)(g_m1h + (size_t)r1 * HID + c) =
                __floats2half2_rn(acc[nt][2], acc[nt][3]);
    }
}

// ---------------- agg1: agg1[n] = sum_{e in CSR[n]} ns[src] * m1h[src] -------
// one warp per node; lane l owns halfs [4l,4l+4) (8B uint2) of the 256B row.
// fp16 gather halves L2 traffic; accumulation in fp32.
__global__ void __launch_bounds__(256)
k_agg1() {
    int n = (blockIdx.x * 256 + threadIdx.x) >> 5;
    if (n >= N_NODES) return;
    int l = threadIdx.x & 31;
    int s0 = g_rowptr[n];
    int e1 = g_rowptr[n + 1];
    float4 acc = make_float4(0.f, 0.f, 0.f, 0.f);
    int e = s0;
    for (; e + 3 < e1; e += 4) {
        int sa = g_esrc[e];
        int sb = g_esrc[e + 1];
        int sc = g_esrc[e + 2];
        int sd = g_esrc[e + 3];
        float na = g_ns[sa], nb = g_ns[sb], nc = g_ns[sc], ne = g_ns[sd];
        uint2 ua = *(const uint2*)(g_m1h + (size_t)sa * HID + 4 * l);
        uint2 ub = *(const uint2*)(g_m1h + (size_t)sb * HID + 4 * l);
        uint2 uc = *(const uint2*)(g_m1h + (size_t)sc * HID + 4 * l);
        uint2 ud = *(const uint2*)(g_m1h + (size_t)sd * HID + 4 * l);
        float2 a0 = __half22float2(*(__half2*)&ua.x), a1 = __half22float2(*(__half2*)&ua.y);
        float2 b0 = __half22float2(*(__half2*)&ub.x), b1 = __half22float2(*(__half2*)&ub.y);
        float2 c0 = __half22float2(*(__half2*)&uc.x), c1 = __half22float2(*(__half2*)&uc.y);
        float2 d0 = __half22float2(*(__half2*)&ud.x), d1 = __half22float2(*(__half2*)&ud.y);
        acc.x += (na * a0.x + nb * b0.x) + (nc * c0.x + ne * d0.x);
        acc.y += (na * a0.y + nb * b0.y) + (nc * c0.y + ne * d0.y);
        acc.z += (na * a1.x + nb * b1.x) + (nc * c1.x + ne * d1.x);
        acc.w += (na * a1.y + nb * b1.y) + (nc * c1.y + ne * d1.y);
    }
    for (; e < e1; e++) {
        int sa = g_esrc[e];
        float na = g_ns[sa];
        uint2 ua = *(const uint2*)(g_m1h + (size_t)sa * HID + 4 * l);
        float2 a0 = __half22float2(*(__half2*)&ua.x), a1 = __half22float2(*(__half2*)&ua.y);
        acc.x += na * a0.x; acc.y += na * a0.y;
        acc.z += na * a1.x; acc.w += na * a1.y;
    }
    ((float4*)(g_agg1 + (size_t)n * HID))[l] = acc;
}

// ---------------- GEMM2 (tf32 tensor cores): m2 = h @ W2 ---------------------
// h = relu(agg1*nd + b1) * ns, fused into the hs tile load.
__global__ void __launch_bounds__(256)
k_gemm2(const float* __restrict__ b1, const float* __restrict__ W2) {
    __shared__ unsigned hs[KCH][136];   // tf32 bits, [k][m]
    __shared__ unsigned ws[KCH][72];    // tf32 bits, [k][n]
    int t = threadIdx.x;
    int base = blockIdx.x * 128;
    int warp = t >> 5;
    int lane = t & 31;
    int g   = lane >> 2;
    int tig = lane & 3;
    int mw  = warp * 16;

    float acc[8][4];
    #pragma unroll
    for (int nt = 0; nt < 8; nt++)
        #pragma unroll
        for (int i = 0; i < 4; i++) acc[nt][i] = 0.f;

    for (int k0 = 0; k0 < HID; k0 += KCH) {
        __syncthreads();
        #pragma unroll
        for (int f = t; f < 512; f += 256) {
            int kk = f >> 4;
            int nn = (f & 15) * 4;
            float4 w = *(const float4*)(W2 + (k0 + kk) * OUT_F + nn);
            ws[kk][nn + 0] = f2tf32(w.x);
            ws[kk][nn + 1] = f2tf32(w.y);
            ws[kk][nn + 2] = f2tf32(w.z);
            ws[kk][nn + 3] = f2tf32(w.w);
        }
        #pragma unroll
        for (int f = t; f < 1024; f += 256) {
            int mm = f >> 3;
            int k4 = (f & 7) * 4;
            int node = base + mm; if (node >= N_NODES) node = N_NODES - 1;
            float nd = g_nd[node];
            float ns = g_ns[node];
            float4 v  = *(const float4*)(g_agg1 + (size_t)node * HID + k0 + k4);
            float4 bv = *(const float4*)(b1 + k0 + k4);
            hs[k4 + 0][mm] = f2tf32(fmaxf(v.x * nd + bv.x, 0.f) * ns);
            hs[k4 + 1][mm] = f2tf32(fmaxf(v.y * nd + bv.y, 0.f) * ns);
            hs[k4 + 2][mm] = f2tf32(fmaxf(v.z * nd + bv.z, 0.f) * ns);
            hs[k4 + 3][mm] = f2tf32(fmaxf(v.w * nd + bv.w, 0.f) * ns);
        }
        __syncthreads();
        #pragma unroll
        for (int ks = 0; ks < KCH / 8; ks++) {
            int kb = ks * 8;
            unsigned a[4];
            a[0] = hs[kb + tig][mw + g];
            a[1] = hs[kb + tig][mw + g + 8];
            a[2] = hs[kb + tig + 4][mw + g];
            a[3] = hs[kb + tig + 4][mw + g + 8];
            #pragma unroll
            for (int nt = 0; nt < 8; nt++) {
                unsigned b0 = ws[kb + tig][nt * 8 + g];
                unsigned b1r = ws[kb + tig + 4][nt * 8 + g];
                mma_tf32(acc[nt], a, b0, b1r);
            }
        }
    }
    int r0 = base + mw + g;
    int r1 = r0 + 8;
    #pragma unroll
    for (int nt = 0; nt < 8; nt++) {
        int c = nt * 8 + tig * 2;
        if (r0 < N_NODES)
            *(float2*)(g_m2 + (size_t)r0 * OUT_F + c) = make_float2(acc[nt][0], acc[nt][1]);
        if (r1 < N_NODES)
            *(float2*)(g_m2 + (size_t)r1 * OUT_F + c) = make_float2(acc[nt][2], acc[nt][3]);
    }
}

// ---------------- agg2 + finalize: out = (gather-sum m2) * nd + b2 -----------
__global__ void __launch_bounds__(256)
k_agg2(float* __restrict__ out, const float* __restrict__ b2) {
    int n = (blockIdx.x * 256 + threadIdx.x) >> 5;
    if (n >= N_NODES) return;
    int l = threadIdx.x & 31;
    int s0 = g_rowptr[n];
    int e1 = g_rowptr[n + 1];
    float2 acc = make_float2(0.f, 0.f);
    int e = s0;
    for (; e + 3 < e1; e += 4) {
        int sa = g_esrc[e];
        int sb = g_esrc[e + 1];
        int sc = g_esrc[e + 2];
        int sd = g_esrc[e + 3];
        float2 va = ((const float2*)(g_m2 + (size_t)sa * OUT_F))[l];
        float2 vb = ((const float2*)(g_m2 + (size_t)sb * OUT_F))[l];
        float2 vc = ((const float2*)(g_m2 + (size_t)sc * OUT_F))[l];
        float2 vd = ((const float2*)(g_m2 + (size_t)sd * OUT_F))[l];
        acc.x += (va.x + vb.x) + (vc.x + vd.x);
        acc.y += (va.y + vb.y) + (vc.y + vd.y);
    }
    for (; e < e1; e++) {
        int sa = g_esrc[e];
        float2 va = ((const float2*)(g_m2 + (size_t)sa * OUT_F))[l];
        acc.x += va.x; acc.y += va.y;
    }
    float nd = g_nd[n];
    float2 bv = ((const float2*)b2)[l];
    float2 r;
    r.x = acc.x * nd + bv.x;
    r.y = acc.y * nd + bv.y;
    ((float2*)(out + (size_t)n * OUT_F))[l] = r;
}

// ---------------- launch -----------------------------------------------------
extern "C" void kernel_launch(void* const* d_in, const int* in_sizes, int n_in,
                              void* d_out, int out_size) {
    // Identify inputs by element count (robust to any metadata ordering).
    const float *x = 0, *W1 = 0, *b1 = 0, *W2 = 0, *b2 = 0;
    const void *srcp = 0, *dstp = 0;
    for (int i = 0; i < n_in; i++) {
        switch (in_sizes[i]) {
            case N_NODES * IN_F: x  = (const float*)d_in[i]; break;   // 12,800,000
            case IN_F * HID:     W1 = (const float*)d_in[i]; break;   // 32,768
            case HID * OUT_F:    W2 = (const float*)d_in[i]; break;   // 8,192
            case HID:            b1 = (const float*)d_in[i]; break;   // 128
            case OUT_F:          b2 = (const float*)d_in[i]; break;   // 64
            case N_EDGES:                                              // 800,000 (x2)
                if (!srcp) srcp = d_in[i]; else dstp = d_in[i];
                break;
            default: break;
        }
    }
    float* out = (float*)d_out;

    // One-time side-stream + events (host objects only; created outside capture
    // on the harness's eager correctness call, reused during capture/replay).
    static cudaStream_t s2 = 0;
    static cudaEvent_t evFork = 0, evJoin = 0;
    if (!s2) {
        cudaStreamCreateWithFlags(&s2, cudaStreamNonBlocking);
        cudaEventCreateWithFlags(&evFork, cudaEventDisableTiming);
        cudaEventCreateWithFlags(&evJoin, cudaEventDisableTiming);
    }

    // Fork: gemm1 (x @ W1, no CSR dependency) overlaps the whole CSR build.
    cudaEventRecord(evFork, 0);
    cudaStreamWaitEvent(s2, evFork, 0);
    k_gemm1<<<(N_NODES + 127) / 128, 256, 0, s2>>>(x, W1);
    cudaEventRecord(evJoin, s2);

    // Main stream: CSR build chain.
    k_initdetect<<<(N_EDGES / 2 + 255) / 256, 256>>>((const int*)srcp, (const int*)dstp);
    k_cvtdeg<<<(N_EDGES + 255) / 256, 256>>>(srcp, dstp);
    k_scan1<<<SCAN_NBLK, SCAN_B>>>();
    k_scan3<<<SCAN_NBLK, SCAN_B>>>();
    k_fill<<<(N_EDGES + 255) / 256, 256>>>();

    // Join: agg1 needs both m1 (s2) and the CSR (main).
    cudaStreamWaitEvent(0, evJoin, 0);
    k_agg1<<<(N_NODES * 32) / 256, 256>>>();
    k_gemm2<<<(N_NODES + 127) / 128, 256>>>(b1, W2);
    k_agg2<<<(N_NODES * 32) / 256, 256>>>(out, b2);
}

// round 16
// speedup vs baseline: 1.8340x; 1.0172x over previous
#include <cuda_runtime.h>
#include <cuda_fp16.h>
#include <cstdint>

#define N_NODES 50000
#define N_EDGES 800000
#define IN_F 256
#define HID 128
#define OUT_F 64

#define SCAN_B 512
#define SCAN_NBLK ((N_NODES + SCAN_B - 1) / SCAN_B)   // 98

// ---------------- scratch (device globals; no allocs allowed) ----------------
__device__ __align__(16) __half g_m1h[(size_t)N_NODES * HID];   // x @ W1, fp16
__device__ __align__(16) float g_agg1[(size_t)N_NODES * HID];   // gather accum, layer 1
__device__ __align__(16) __half g_m2h[(size_t)N_NODES * OUT_F]; // (h*ns) @ W2, fp16
__device__ float g_ns[N_NODES];                  // deg_out^-1/2 (clamped)
__device__ float g_nd[N_NODES];                  // deg_in^-1/2 (clamped)
__device__ int   g_degs[N_NODES];                // out-degree (src)
__device__ int   g_degd[N_NODES];                // in-degree (dst)
__device__ int   g_rowptr[N_NODES + 1];          // CSR by dst
__device__ int   g_esrc[N_EDGES];                // src id per bucketed edge
__device__ int   g_src[N_EDGES];                 // normalized (int, clamped) src
__device__ int   g_dst[N_EDGES];                 // normalized (int, clamped) dst
__device__ int   g_rank[N_EDGES];                // within-dst-bucket rank
__device__ int   g_bsum[SCAN_NBLK];
__device__ int   g_is32;                         // sticky: 1 if indices are int32

// ---------------- tf32 helpers ----------------------------------------------
__device__ __forceinline__ unsigned f2tf32(float f) {
    unsigned r;
    asm("cvt.rna.tf32.f32 %0, %1;" : "=r"(r) : "f"(f));
    return r;
}
__device__ __forceinline__ void mma_tf32(float* d, const unsigned* a,
                                         unsigned b0, unsigned b1) {
    asm("mma.sync.aligned.m16n8k8.row.col.f32.tf32.tf32.f32 "
        "{%0,%1,%2,%3}, {%4,%5,%6,%7}, {%8,%9}, {%0,%1,%2,%3};"
        : "+f"(d[0]), "+f"(d[1]), "+f"(d[2]), "+f"(d[3])
        : "r"(a[0]), "r"(a[1]), "r"(a[2]), "r"(a[3]), "r"(b0), "r"(b1));
}

// ---------------- init degrees + dtype detect (fused) ------------------------
__global__ void k_initdetect(const int* __restrict__ sw, const int* __restrict__ dw) {
    int t = blockIdx.x * 256 + threadIdx.x;
    if (t < N_NODES) { g_degs[t] = 0; g_degd[t] = 0; }
    int v = 0;
    if (t < N_EDGES / 2) v = sw[2 * t + 1] | dw[2 * t + 1];
    unsigned any = __ballot_sync(0xffffffffu, v != 0);
    if ((threadIdx.x & 31) == 0 && any) atomicOr(&g_is32, 1);
}

// ---------------- normalize indices + degrees + bucket rank (fused) ----------
__global__ void k_cvtdeg(const void* __restrict__ srcp, const void* __restrict__ dstp) {
    int e = blockIdx.x * 256 + threadIdx.x;
    if (e >= N_EDGES) return;
    int s, d;
    if (g_is32) {
        s = ((const int*)srcp)[e];
        d = ((const int*)dstp)[e];
    } else {
        s = (int)((const long long*)srcp)[e];
        d = (int)((const long long*)dstp)[e];
    }
    s = min(max(s, 0), N_NODES - 1);
    d = min(max(d, 0), N_NODES - 1);
    g_src[e] = s;
    g_dst[e] = d;
    atomicAdd(&g_degs[s], 1);
    g_rank[e] = atomicAdd(&g_degd[d], 1);
}

// ---------------- scan pass 1: shuffle-based block scan + norms --------------
__global__ void k_scan1() {
    __shared__ int wsum[16];
    int t = threadIdx.x;
    int lane = t & 31;
    int w = t >> 5;
    int i = blockIdx.x * SCAN_B + t;
    int v = (i < N_NODES) ? g_degd[i] : 0;
    int sc = v;
    #pragma unroll
    for (int o = 1; o < 32; o <<= 1) {
        int u = __shfl_up_sync(0xffffffffu, sc, o);
        if (lane >= o) sc += u;
    }
    if (lane == 31) wsum[w] = sc;
    __syncthreads();
    if (w == 0) {
        int ws = (lane < 16) ? wsum[lane] : 0;
        #pragma unroll
        for (int o = 1; o < 16; o <<= 1) {
            int u = __shfl_up_sync(0xffffffffu, ws, o);
            if (lane >= o) ws += u;
        }
        if (lane < 16) wsum[lane] = ws;
    }
    __syncthreads();
    int incl = sc + (w > 0 ? wsum[w - 1] : 0);
    if (i < N_NODES) {
        g_rowptr[i] = incl - v;   // exclusive
        int ds = g_degs[i]; if (ds < 1) ds = 1;
        int dd = v;         if (dd < 1) dd = 1;
        g_ns[i] = rsqrtf((float)ds);
        g_nd[i] = rsqrtf((float)dd);
    }
    if (t == SCAN_B - 1) g_bsum[blockIdx.x] = incl;
}

// ---------------- scan pass 2: per-block prefix of bsum + apply --------------
__global__ void k_scan3() {
    __shared__ int warpsum[4];
    int t = threadIdx.x;
    int v = 0;
    if (t < 128) {
        if (t < SCAN_NBLK && t < (int)blockIdx.x) v = g_bsum[t];
        #pragma unroll
        for (int o = 16; o > 0; o >>= 1) v += __shfl_down_sync(0xffffffffu, v, o);
        if ((t & 31) == 0) warpsum[t >> 5] = v;
    }
    __syncthreads();
    int off = warpsum[0] + warpsum[1] + warpsum[2] + warpsum[3];
    int i = blockIdx.x * SCAN_B + t;
    if (i < N_NODES) g_rowptr[i] += off;
    if (i == 0) g_rowptr[N_NODES] = N_EDGES;
}

// ---------------- bucket fill: atomic-free (rank precomputed) ----------------
__global__ void k_fill() {
    int e = blockIdx.x * blockDim.x + threadIdx.x;
    if (e >= N_EDGES) return;
    int d = g_dst[e];
    g_esrc[g_rowptr[d] + g_rank[e]] = g_src[e];
}

// ---------------- GEMM1 (tf32 tensor cores): m1 = x @ W1, fp16 out -----------
#define KCH 32
__global__ void __launch_bounds__(256)
k_gemm1(const float* __restrict__ x, const float* __restrict__ W1) {
    __shared__ unsigned xs[KCH][136];   // tf32 bits, [k][m]
    __shared__ unsigned ws[KCH][136];   // tf32 bits, [k][n]
    int t = threadIdx.x;
    int base = blockIdx.x * 128;
    int warp = t >> 5;
    int lane = t & 31;
    int g   = lane >> 2;    // 0..7
    int tig = lane & 3;     // 0..3
    int mw  = warp * 16;

    float acc[16][4];
    #pragma unroll
    for (int nt = 0; nt < 16; nt++)
        #pragma unroll
        for (int i = 0; i < 4; i++) acc[nt][i] = 0.f;

    for (int k0 = 0; k0 < IN_F; k0 += KCH) {
        __syncthreads();
        #pragma unroll
        for (int f = t; f < 1024; f += 256) {
            int kk = f >> 5;
            int nn = (f & 31) * 4;
            float4 w = *(const float4*)(W1 + (k0 + kk) * HID + nn);
            ws[kk][nn + 0] = f2tf32(w.x);
            ws[kk][nn + 1] = f2tf32(w.y);
            ws[kk][nn + 2] = f2tf32(w.z);
            ws[kk][nn + 3] = f2tf32(w.w);
        }
        #pragma unroll
        for (int f = t; f < 1024; f += 256) {
            int mm = f >> 3;
            int k4 = (f & 7) * 4;
            int node = base + mm; if (node >= N_NODES) node = N_NODES - 1;
            float4 v = *(const float4*)(x + (size_t)node * IN_F + k0 + k4);
            xs[k4 + 0][mm] = f2tf32(v.x);
            xs[k4 + 1][mm] = f2tf32(v.y);
            xs[k4 + 2][mm] = f2tf32(v.z);
            xs[k4 + 3][mm] = f2tf32(v.w);
        }
        __syncthreads();
        #pragma unroll
        for (int ks = 0; ks < KCH / 8; ks++) {
            int kb = ks * 8;
            unsigned a[4];
            a[0] = xs[kb + tig][mw + g];
            a[1] = xs[kb + tig][mw + g + 8];
            a[2] = xs[kb + tig + 4][mw + g];
            a[3] = xs[kb + tig + 4][mw + g + 8];
            #pragma unroll
            for (int nt = 0; nt < 16; nt++) {
                unsigned b0 = ws[kb + tig][nt * 8 + g];
                unsigned b1 = ws[kb + tig + 4][nt * 8 + g];
                mma_tf32(acc[nt], a, b0, b1);
            }
        }
    }
    int r0 = base + mw + g;
    int r1 = r0 + 8;
    #pragma unroll
    for (int nt = 0; nt < 16; nt++) {
        int c = nt * 8 + tig * 2;
        if (r0 < N_NODES)
            *(__half2*)(g_m1h + (size_t)r0 * HID + c) =
                __floats2half2_rn(acc[nt][0], acc[nt][1]);
        if (r1 < N_NODES)
            *(__half2*)(g_m1h + (size_t)r1 * HID + c) =
                __floats2half2_rn(acc[nt][2], acc[nt][3]);
    }
}

// ---------------- agg1: agg1[n] = sum_{e in CSR[n]} ns[src] * m1h[src] -------
// one warp per node; lane l owns halfs [4l,4l+4) (8B uint2) of the 256B row.
__global__ void __launch_bounds__(256)
k_agg1() {
    int n = (blockIdx.x * 256 + threadIdx.x) >> 5;
    if (n >= N_NODES) return;
    int l = threadIdx.x & 31;
    int s0 = g_rowptr[n];
    int e1 = g_rowptr[n + 1];
    float4 acc = make_float4(0.f, 0.f, 0.f, 0.f);
    int e = s0;
    for (; e + 3 < e1; e += 4) {
        int sa = g_esrc[e];
        int sb = g_esrc[e + 1];
        int sc = g_esrc[e + 2];
        int sd = g_esrc[e + 3];
        float na = g_ns[sa], nb = g_ns[sb], nc = g_ns[sc], ne = g_ns[sd];
        uint2 ua = *(const uint2*)(g_m1h + (size_t)sa * HID + 4 * l);
        uint2 ub = *(const uint2*)(g_m1h + (size_t)sb * HID + 4 * l);
        uint2 uc = *(const uint2*)(g_m1h + (size_t)sc * HID + 4 * l);
        uint2 ud = *(const uint2*)(g_m1h + (size_t)sd * HID + 4 * l);
        float2 a0 = __half22float2(*(__half2*)&ua.x), a1 = __half22float2(*(__half2*)&ua.y);
        float2 b0 = __half22float2(*(__half2*)&ub.x), b1 = __half22float2(*(__half2*)&ub.y);
        float2 c0 = __half22float2(*(__half2*)&uc.x), c1 = __half22float2(*(__half2*)&uc.y);
        float2 d0 = __half22float2(*(__half2*)&ud.x), d1 = __half22float2(*(__half2*)&ud.y);
        acc.x += (na * a0.x + nb * b0.x) + (nc * c0.x + ne * d0.x);
        acc.y += (na * a0.y + nb * b0.y) + (nc * c0.y + ne * d0.y);
        acc.z += (na * a1.x + nb * b1.x) + (nc * c1.x + ne * d1.x);
        acc.w += (na * a1.y + nb * b1.y) + (nc * c1.y + ne * d1.y);
    }
    for (; e < e1; e++) {
        int sa = g_esrc[e];
        float na = g_ns[sa];
        uint2 ua = *(const uint2*)(g_m1h + (size_t)sa * HID + 4 * l);
        float2 a0 = __half22float2(*(__half2*)&ua.x), a1 = __half22float2(*(__half2*)&ua.y);
        acc.x += na * a0.x; acc.y += na * a0.y;
        acc.z += na * a1.x; acc.w += na * a1.y;
    }
    ((float4*)(g_agg1 + (size_t)n * HID))[l] = acc;
}

// ---------------- GEMM2 (tf32 tensor cores): m2 = h @ W2, fp16 out -----------
__global__ void __launch_bounds__(256)
k_gemm2(const float* __restrict__ b1, const float* __restrict__ W2) {
    __shared__ unsigned hs[KCH][136];   // tf32 bits, [k][m]
    __shared__ unsigned ws[KCH][72];    // tf32 bits, [k][n]
    int t = threadIdx.x;
    int base = blockIdx.x * 128;
    int warp = t >> 5;
    int lane = t & 31;
    int g   = lane >> 2;
    int tig = lane & 3;
    int mw  = warp * 16;

    float acc[8][4];
    #pragma unroll
    for (int nt = 0; nt < 8; nt++)
        #pragma unroll
        for (int i = 0; i < 4; i++) acc[nt][i] = 0.f;

    for (int k0 = 0; k0 < HID; k0 += KCH) {
        __syncthreads();
        #pragma unroll
        for (int f = t; f < 512; f += 256) {
            int kk = f >> 4;
            int nn = (f & 15) * 4;
            float4 w = *(const float4*)(W2 + (k0 + kk) * OUT_F + nn);
            ws[kk][nn + 0] = f2tf32(w.x);
            ws[kk][nn + 1] = f2tf32(w.y);
            ws[kk][nn + 2] = f2tf32(w.z);
            ws[kk][nn + 3] = f2tf32(w.w);
        }
        #pragma unroll
        for (int f = t; f < 1024; f += 256) {
            int mm = f >> 3;
            int k4 = (f & 7) * 4;
            int node = base + mm; if (node >= N_NODES) node = N_NODES - 1;
            float nd = g_nd[node];
            float ns = g_ns[node];
            float4 v  = *(const float4*)(g_agg1 + (size_t)node * HID + k0 + k4);
            float4 bv = *(const float4*)(b1 + k0 + k4);
            hs[k4 + 0][mm] = f2tf32(fmaxf(v.x * nd + bv.x, 0.f) * ns);
            hs[k4 + 1][mm] = f2tf32(fmaxf(v.y * nd + bv.y, 0.f) * ns);
            hs[k4 + 2][mm] = f2tf32(fmaxf(v.z * nd + bv.z, 0.f) * ns);
            hs[k4 + 3][mm] = f2tf32(fmaxf(v.w * nd + bv.w, 0.f) * ns);
        }
        __syncthreads();
        #pragma unroll
        for (int ks = 0; ks < KCH / 8; ks++) {
            int kb = ks * 8;
            unsigned a[4];
            a[0] = hs[kb + tig][mw + g];
            a[1] = hs[kb + tig][mw + g + 8];
            a[2] = hs[kb + tig + 4][mw + g];
            a[3] = hs[kb + tig + 4][mw + g + 8];
            #pragma unroll
            for (int nt = 0; nt < 8; nt++) {
                unsigned b0 = ws[kb + tig][nt * 8 + g];
                unsigned b1r = ws[kb + tig + 4][nt * 8 + g];
                mma_tf32(acc[nt], a, b0, b1r);
            }
        }
    }
    int r0 = base + mw + g;
    int r1 = r0 + 8;
    #pragma unroll
    for (int nt = 0; nt < 8; nt++) {
        int c = nt * 8 + tig * 2;
        if (r0 < N_NODES)
            *(__half2*)(g_m2h + (size_t)r0 * OUT_F + c) =
                __floats2half2_rn(acc[nt][0], acc[nt][1]);
        if (r1 < N_NODES)
            *(__half2*)(g_m2h + (size_t)r1 * OUT_F + c) =
                __floats2half2_rn(acc[nt][2], acc[nt][3]);
    }
}

// ---------------- agg2 + finalize: out = (gather-sum m2h) * nd + b2 ----------
// HALF-WARP per node: 16 lanes x 8B (uint2 of half2) covers the 128B fp16 row.
// 2x node parallelism + 2x outstanding loads vs warp-per-node.
__global__ void __launch_bounds__(256)
k_agg2(float* __restrict__ out, const float* __restrict__ b2) {
    int tid = blockIdx.x * 256 + threadIdx.x;
    int n = tid >> 4;
    if (n >= N_NODES) return;
    int l = tid & 15;
    int s0 = g_rowptr[n];
    int e1 = g_rowptr[n + 1];
    float4 acc = make_float4(0.f, 0.f, 0.f, 0.f);
    int e = s0;
    for (; e + 3 < e1; e += 4) {
        int sa = g_esrc[e];
        int sb = g_esrc[e + 1];
        int sc = g_esrc[e + 2];
        int sd = g_esrc[e + 3];
        uint2 ua = *(const uint2*)(g_m2h + (size_t)sa * OUT_F + 4 * l);
        uint2 ub = *(const uint2*)(g_m2h + (size_t)sb * OUT_F + 4 * l);
        uint2 uc = *(const uint2*)(g_m2h + (size_t)sc * OUT_F + 4 * l);
        uint2 ud = *(const uint2*)(g_m2h + (size_t)sd * OUT_F + 4 * l);
        float2 a0 = __half22float2(*(__half2*)&ua.x), a1 = __half22float2(*(__half2*)&ua.y);
        float2 b0 = __half22float2(*(__half2*)&ub.x), b1 = __half22float2(*(__half2*)&ub.y);
        float2 c0 = __half22float2(*(__half2*)&uc.x), c1 = __half22float2(*(__half2*)&uc.y);
        float2 d0 = __half22float2(*(__half2*)&ud.x), d1 = __half22float2(*(__half2*)&ud.y);
        acc.x += (a0.x + b0.x) + (c0.x + d0.x);
        acc.y += (a0.y + b0.y) + (c0.y + d0.y);
        acc.z += (a1.x + b1.x) + (c1.x + d1.x);
        acc.w += (a1.y + b1.y) + (c1.y + d1.y);
    }
    for (; e < e1; e++) {
        int sa = g_esrc[e];
        uint2 ua = *(const uint2*)(g_m2h + (size_t)sa * OUT_F + 4 * l);
        float2 a0 = __half22float2(*(__half2*)&ua.x), a1 = __half22float2(*(__half2*)&ua.y);
        acc.x += a0.x; acc.y += a0.y; acc.z += a1.x; acc.w += a1.y;
    }
    float nd = g_nd[n];
    float4 bv = ((const float4*)b2)[l];
    float4 r;
    r.x = acc.x * nd + bv.x;
    r.y = acc.y * nd + bv.y;
    r.z = acc.z * nd + bv.z;
    r.w = acc.w * nd + bv.w;
    ((float4*)(out + (size_t)n * OUT_F))[l] = r;
}

// ---------------- launch -----------------------------------------------------
extern "C" void kernel_launch(void* const* d_in, const int* in_sizes, int n_in,
                              void* d_out, int out_size) {
    // Identify inputs by element count (robust to any metadata ordering).
    const float *x = 0, *W1 = 0, *b1 = 0, *W2 = 0, *b2 = 0;
    const void *srcp = 0, *dstp = 0;
    for (int i = 0; i < n_in; i++) {
        switch (in_sizes[i]) {
            case N_NODES * IN_F: x  = (const float*)d_in[i]; break;   // 12,800,000
            case IN_F * HID:     W1 = (const float*)d_in[i]; break;   // 32,768
            case HID * OUT_F:    W2 = (const float*)d_in[i]; break;   // 8,192
            case HID:            b1 = (const float*)d_in[i]; break;   // 128
            case OUT_F:          b2 = (const float*)d_in[i]; break;   // 64
            case N_EDGES:                                              // 800,000 (x2)
                if (!srcp) srcp = d_in[i]; else dstp = d_in[i];
                break;
            default: break;
        }
    }
    float* out = (float*)d_out;

    // One-time side-stream + events (host objects only; created outside capture
    // on the harness's eager correctness call, reused during capture/replay).
    static cudaStream_t s2 = 0;
    static cudaEvent_t evFork = 0, evJoin = 0;
    if (!s2) {
        cudaStreamCreateWithFlags(&s2, cudaStreamNonBlocking);
        cudaEventCreateWithFlags(&evFork, cudaEventDisableTiming);
        cudaEventCreateWithFlags(&evJoin, cudaEventDisableTiming);
    }

    // Fork: gemm1 (x @ W1, no CSR dependency) overlaps the whole CSR build.
    cudaEventRecord(evFork, 0);
    cudaStreamWaitEvent(s2, evFork, 0);
    k_gemm1<<<(N_NODES + 127) / 128, 256, 0, s2>>>(x, W1);
    cudaEventRecord(evJoin, s2);

    // Main stream: CSR build chain.
    k_initdetect<<<(N_EDGES / 2 + 255) / 256, 256>>>((const int*)srcp, (const int*)dstp);
    k_cvtdeg<<<(N_EDGES + 255) / 256, 256>>>(srcp, dstp);
    k_scan1<<<SCAN_NBLK, SCAN_B>>>();
    k_scan3<<<SCAN_NBLK, SCAN_B>>>();
    k_fill<<<(N_EDGES + 255) / 256, 256>>>();

    // Join: agg1 needs both m1 (s2) and the CSR (main).
    cudaStreamWaitEvent(0, evJoin, 0);
    k_agg1<<<(N_NODES * 32) / 256, 256>>>();
    k_gemm2<<<(N_NODES + 127) / 128, 256>>>(b1, W2);
    k_agg2<<<(N_NODES * 16 + 255) / 256, 256>>>(out, b2);
}

// round 17
// speedup vs baseline: 1.9074x; 1.0400x over previous
#include <cuda_runtime.h>
#include <cuda_fp16.h>
#include <cstdint>

#define N_NODES 50000
#define N_EDGES 800000
#define IN_F 256
#define HID 128
#define OUT_F 64

#define SCAN_B 512
#define SCAN_NBLK ((N_NODES + SCAN_B - 1) / SCAN_B)   // 98
#define DETECT_N 8192

// ---------------- scratch (device globals; no allocs allowed) ----------------
__device__ __align__(16) __half g_m1h[(size_t)N_NODES * HID];    // x @ W1, fp16
__device__ __align__(16) __half g_agg1h[(size_t)N_NODES * HID];  // gather accum, fp16
__device__ __align__(16) __half g_m2h[(size_t)N_NODES * OUT_F];  // (h*ns) @ W2, fp16
__device__ float g_ns[N_NODES];                  // deg_out^-1/2 (clamped)
__device__ float g_nd[N_NODES];                  // deg_in^-1/2 (clamped)
__device__ int   g_degs[N_NODES];                // out-degree (src)
__device__ int   g_degd[N_NODES];                // in-degree (dst)
__device__ int   g_rowptr[N_NODES + 1];          // CSR by dst
__device__ int   g_esrc[N_EDGES];                // src id per bucketed edge
__device__ int   g_src[N_EDGES];                 // normalized (int, clamped) src
__device__ unsigned g_dr[N_EDGES];               // packed: dst | (bucket-rank << 16)
__device__ int   g_bsum[SCAN_NBLK];
__device__ int   g_is32;                         // sticky: 1 if indices are int32

// ---------------- tf32 helpers ----------------------------------------------
__device__ __forceinline__ unsigned f2tf32(float f) {
    unsigned r;
    asm("cvt.rna.tf32.f32 %0, %1;" : "=r"(r) : "f"(f));
    return r;
}
__device__ __forceinline__ void mma_tf32(float* d, const unsigned* a,
                                         unsigned b0, unsigned b1) {
    asm("mma.sync.aligned.m16n8k8.row.col.f32.tf32.tf32.f32 "
        "{%0,%1,%2,%3}, {%4,%5,%6,%7}, {%8,%9}, {%0,%1,%2,%3};"
        : "+f"(d[0]), "+f"(d[1]), "+f"(d[2]), "+f"(d[3])
        : "r"(a[0]), "r"(a[1]), "r"(a[2]), "r"(a[3]), "r"(b0), "r"(b1));
}

// ---------------- init degrees + SAMPLED dtype detect (fused) ----------------
// int64 indices < 2^31 have all-zero odd words; int32 data has random node ids
// there. 8192 samples decide with certainty; avoids streaming 12.8 MB.
__global__ void k_initdetect(const int* __restrict__ sw, const int* __restrict__ dw) {
    int t = blockIdx.x * 256 + threadIdx.x;
    if (t < N_NODES) { g_degs[t] = 0; g_degd[t] = 0; }
    int v = 0;
    if (t < DETECT_N) v = sw[2 * t + 1] | dw[2 * t + 1];
    unsigned any = __ballot_sync(0xffffffffu, v != 0);
    if ((threadIdx.x & 31) == 0 && any) atomicOr(&g_is32, 1);
}

// ---------------- normalize indices + degrees + packed bucket rank -----------
__global__ void k_cvtdeg(const void* __restrict__ srcp, const void* __restrict__ dstp) {
    int e = blockIdx.x * 256 + threadIdx.x;
    if (e >= N_EDGES) return;
    int s, d;
    if (g_is32) {
        s = ((const int*)srcp)[e];
        d = ((const int*)dstp)[e];
    } else {
        s = (int)((const long long*)srcp)[e];
        d = (int)((const long long*)dstp)[e];
    }
    s = min(max(s, 0), N_NODES - 1);
    d = min(max(d, 0), N_NODES - 1);
    g_src[e] = s;
    atomicAdd(&g_degs[s], 1);
    unsigned rank = (unsigned)atomicAdd(&g_degd[d], 1);
    g_dr[e] = (unsigned)d | (rank << 16);     // N_NODES < 2^16; rank << 2^16 here
}

// ---------------- scan pass 1: shuffle-based block scan + norms --------------
__global__ void k_scan1() {
    __shared__ int wsum[16];
    int t = threadIdx.x;
    int lane = t & 31;
    int w = t >> 5;
    int i = blockIdx.x * SCAN_B + t;
    int v = (i < N_NODES) ? g_degd[i] : 0;
    int sc = v;
    #pragma unroll
    for (int o = 1; o < 32; o <<= 1) {
        int u = __shfl_up_sync(0xffffffffu, sc, o);
        if (lane >= o) sc += u;
    }
    if (lane == 31) wsum[w] = sc;
    __syncthreads();
    if (w == 0) {
        int ws = (lane < 16) ? wsum[lane] : 0;
        #pragma unroll
        for (int o = 1; o < 16; o <<= 1) {
            int u = __shfl_up_sync(0xffffffffu, ws, o);
            if (lane >= o) ws += u;
        }
        if (lane < 16) wsum[lane] = ws;
    }
    __syncthreads();
    int incl = sc + (w > 0 ? wsum[w - 1] : 0);
    if (i < N_NODES) {
        g_rowptr[i] = incl - v;   // exclusive
        int ds = g_degs[i]; if (ds < 1) ds = 1;
        int dd = v;         if (dd < 1) dd = 1;
        g_ns[i] = rsqrtf((float)ds);
        g_nd[i] = rsqrtf((float)dd);
    }
    if (t == SCAN_B - 1) g_bsum[blockIdx.x] = incl;
}

// ---------------- scan pass 2: per-block prefix of bsum + apply --------------
__global__ void k_scan3() {
    __shared__ int warpsum[4];
    int t = threadIdx.x;
    int v = 0;
    if (t < 128) {
        if (t < SCAN_NBLK && t < (int)blockIdx.x) v = g_bsum[t];
        #pragma unroll
        for (int o = 16; o > 0; o >>= 1) v += __shfl_down_sync(0xffffffffu, v, o);
        if ((t & 31) == 0) warpsum[t >> 5] = v;
    }
    __syncthreads();
    int off = warpsum[0] + warpsum[1] + warpsum[2] + warpsum[3];
    int i = blockIdx.x * SCAN_B + t;
    if (i < N_NODES) g_rowptr[i] += off;
    if (i == 0) g_rowptr[N_NODES] = N_EDGES;
}

// ---------------- bucket fill: atomic-free (packed dst+rank) -----------------
__global__ void k_fill() {
    int e = blockIdx.x * blockDim.x + threadIdx.x;
    if (e >= N_EDGES) return;
    unsigned dr = g_dr[e];
    int d = (int)(dr & 0xFFFFu);
    int rank = (int)(dr >> 16);
    g_esrc[g_rowptr[d] + rank] = g_src[e];
}

// ---------------- GEMM1 (tf32 tensor cores): m1 = x @ W1, fp16 out -----------
#define KCH 32
__global__ void __launch_bounds__(256)
k_gemm1(const float* __restrict__ x, const float* __restrict__ W1) {
    __shared__ unsigned xs[KCH][136];   // tf32 bits, [k][m]
    __shared__ unsigned ws[KCH][136];   // tf32 bits, [k][n]
    int t = threadIdx.x;
    int base = blockIdx.x * 128;
    int warp = t >> 5;
    int lane = t & 31;
    int g   = lane >> 2;    // 0..7
    int tig = lane & 3;     // 0..3
    int mw  = warp * 16;

    float acc[16][4];
    #pragma unroll
    for (int nt = 0; nt < 16; nt++)
        #pragma unroll
        for (int i = 0; i < 4; i++) acc[nt][i] = 0.f;

    for (int k0 = 0; k0 < IN_F; k0 += KCH) {
        __syncthreads();
        #pragma unroll
        for (int f = t; f < 1024; f += 256) {
            int kk = f >> 5;
            int nn = (f & 31) * 4;
            float4 w = *(const float4*)(W1 + (k0 + kk) * HID + nn);
            ws[kk][nn + 0] = f2tf32(w.x);
            ws[kk][nn + 1] = f2tf32(w.y);
            ws[kk][nn + 2] = f2tf32(w.z);
            ws[kk][nn + 3] = f2tf32(w.w);
        }
        #pragma unroll
        for (int f = t; f < 1024; f += 256) {
            int mm = f >> 3;
            int k4 = (f & 7) * 4;
            int node = base + mm; if (node >= N_NODES) node = N_NODES - 1;
            float4 v = *(const float4*)(x + (size_t)node * IN_F + k0 + k4);
            xs[k4 + 0][mm] = f2tf32(v.x);
            xs[k4 + 1][mm] = f2tf32(v.y);
            xs[k4 + 2][mm] = f2tf32(v.z);
            xs[k4 + 3][mm] = f2tf32(v.w);
        }
        __syncthreads();
        #pragma unroll
        for (int ks = 0; ks < KCH / 8; ks++) {
            int kb = ks * 8;
            unsigned a[4];
            a[0] = xs[kb + tig][mw + g];
            a[1] = xs[kb + tig][mw + g + 8];
            a[2] = xs[kb + tig + 4][mw + g];
            a[3] = xs[kb + tig + 4][mw + g + 8];
            #pragma unroll
            for (int nt = 0; nt < 16; nt++) {
                unsigned b0 = ws[kb + tig][nt * 8 + g];
                unsigned b1 = ws[kb + tig + 4][nt * 8 + g];
                mma_tf32(acc[nt], a, b0, b1);
            }
        }
    }
    int r0 = base + mw + g;
    int r1 = r0 + 8;
    #pragma unroll
    for (int nt = 0; nt < 16; nt++) {
        int c = nt * 8 + tig * 2;
        if (r0 < N_NODES)
            *(__half2*)(g_m1h + (size_t)r0 * HID + c) =
                __floats2half2_rn(acc[nt][0], acc[nt][1]);
        if (r1 < N_NODES)
            *(__half2*)(g_m1h + (size_t)r1 * HID + c) =
                __floats2half2_rn(acc[nt][2], acc[nt][3]);
    }
}

// ---------------- agg1: agg1h[n] = sum_{e in CSR[n]} ns[src] * m1h[src] ------
// one warp per node; lane l owns halfs [4l,4l+4); fp32 accumulate, fp16 store.
__global__ void __launch_bounds__(256)
k_agg1() {
    int n = (blockIdx.x * 256 + threadIdx.x) >> 5;
    if (n >= N_NODES) return;
    int l = threadIdx.x & 31;
    int s0 = g_rowptr[n];
    int e1 = g_rowptr[n + 1];
    float4 acc = make_float4(0.f, 0.f, 0.f, 0.f);
    int e = s0;
    for (; e + 3 < e1; e += 4) {
        int sa = g_esrc[e];
        int sb = g_esrc[e + 1];
        int sc = g_esrc[e + 2];
        int sd = g_esrc[e + 3];
        float na = g_ns[sa], nb = g_ns[sb], nc = g_ns[sc], ne = g_ns[sd];
        uint2 ua = *(const uint2*)(g_m1h + (size_t)sa * HID + 4 * l);
        uint2 ub = *(const uint2*)(g_m1h + (size_t)sb * HID + 4 * l);
        uint2 uc = *(const uint2*)(g_m1h + (size_t)sc * HID + 4 * l);
        uint2 ud = *(const uint2*)(g_m1h + (size_t)sd * HID + 4 * l);
        float2 a0 = __half22float2(*(__half2*)&ua.x), a1 = __half22float2(*(__half2*)&ua.y);
        float2 b0 = __half22float2(*(__half2*)&ub.x), b1 = __half22float2(*(__half2*)&ub.y);
        float2 c0 = __half22float2(*(__half2*)&uc.x), c1 = __half22float2(*(__half2*)&uc.y);
        float2 d0 = __half22float2(*(__half2*)&ud.x), d1 = __half22float2(*(__half2*)&ud.y);
        acc.x += (na * a0.x + nb * b0.x) + (nc * c0.x + ne * d0.x);
        acc.y += (na * a0.y + nb * b0.y) + (nc * c0.y + ne * d0.y);
        acc.z += (na * a1.x + nb * b1.x) + (nc * c1.x + ne * d1.x);
        acc.w += (na * a1.y + nb * b1.y) + (nc * c1.y + ne * d1.y);
    }
    for (; e < e1; e++) {
        int sa = g_esrc[e];
        float na = g_ns[sa];
        uint2 ua = *(const uint2*)(g_m1h + (size_t)sa * HID + 4 * l);
        float2 a0 = __half22float2(*(__half2*)&ua.x), a1 = __half22float2(*(__half2*)&ua.y);
        acc.x += na * a0.x; acc.y += na * a0.y;
        acc.z += na * a1.x; acc.w += na * a1.y;
    }
    uint2 o;
    *(__half2*)&o.x = __floats2half2_rn(acc.x, acc.y);
    *(__half2*)&o.y = __floats2half2_rn(acc.z, acc.w);
    *(uint2*)(g_agg1h + (size_t)n * HID + 4 * l) = o;
}

// ---------------- GEMM2 (tf32 tensor cores): m2 = h @ W2, fp16 out -----------
// h = relu(agg1h*nd + b1) * ns, fused into the hs tile load (fp16 source).
__global__ void __launch_bounds__(256)
k_gemm2(const float* __restrict__ b1, const float* __restrict__ W2) {
    __shared__ unsigned hs[KCH][136];   // tf32 bits, [k][m]
    __shared__ unsigned ws[KCH][72];    // tf32 bits, [k][n]
    int t = threadIdx.x;
    int base = blockIdx.x * 128;
    int warp = t >> 5;
    int lane = t & 31;
    int g   = lane >> 2;
    int tig = lane & 3;
    int mw  = warp * 16;

    float acc[8][4];
    #pragma unroll
    for (int nt = 0; nt < 8; nt++)
        #pragma unroll
        for (int i = 0; i < 4; i++) acc[nt][i] = 0.f;

    for (int k0 = 0; k0 < HID; k0 += KCH) {
        __syncthreads();
        #pragma unroll
        for (int f = t; f < 512; f += 256) {
            int kk = f >> 4;
            int nn = (f & 15) * 4;
            float4 w = *(const float4*)(W2 + (k0 + kk) * OUT_F + nn);
            ws[kk][nn + 0] = f2tf32(w.x);
            ws[kk][nn + 1] = f2tf32(w.y);
            ws[kk][nn + 2] = f2tf32(w.z);
            ws[kk][nn + 3] = f2tf32(w.w);
        }
        #pragma unroll
        for (int f = t; f < 1024; f += 256) {
            int mm = f >> 3;
            int k4 = (f & 7) * 4;
            int node = base + mm; if (node >= N_NODES) node = N_NODES - 1;
            float nd = g_nd[node];
            float ns = g_ns[node];
            uint2 u = *(const uint2*)(g_agg1h + (size_t)node * HID + k0 + k4);
            float2 v01 = __half22float2(*(__half2*)&u.x);
            float2 v23 = __half22float2(*(__half2*)&u.y);
            float4 bv = *(const float4*)(b1 + k0 + k4);
            hs[k4 + 0][mm] = f2tf32(fmaxf(v01.x * nd + bv.x, 0.f) * ns);
            hs[k4 + 1][mm] = f2tf32(fmaxf(v01.y * nd + bv.y, 0.f) * ns);
            hs[k4 + 2][mm] = f2tf32(fmaxf(v23.x * nd + bv.z, 0.f) * ns);
            hs[k4 + 3][mm] = f2tf32(fmaxf(v23.y * nd + bv.w, 0.f) * ns);
        }
        __syncthreads();
        #pragma unroll
        for (int ks = 0; ks < KCH / 8; ks++) {
            int kb = ks * 8;
            unsigned a[4];
            a[0] = hs[kb + tig][mw + g];
            a[1] = hs[kb + tig][mw + g + 8];
            a[2] = hs[kb + tig + 4][mw + g];
            a[3] = hs[kb + tig + 4][mw + g + 8];
            #pragma unroll
            for (int nt = 0; nt < 8; nt++) {
                unsigned b0 = ws[kb + tig][nt * 8 + g];
                unsigned b1r = ws[kb + tig + 4][nt * 8 + g];
                mma_tf32(acc[nt], a, b0, b1r);
            }
        }
    }
    int r0 = base + mw + g;
    int r1 = r0 + 8;
    #pragma unroll
    for (int nt = 0; nt < 8; nt++) {
        int c = nt * 8 + tig * 2;
        if (r0 < N_NODES)
            *(__half2*)(g_m2h + (size_t)r0 * OUT_F + c) =
                __floats2half2_rn(acc[nt][0], acc[nt][1]);
        if (r1 < N_NODES)
            *(__half2*)(g_m2h + (size_t)r1 * OUT_F + c) =
                __floats2half2_rn(acc[nt][2], acc[nt][3]);
    }
}

// ---------------- agg2 + finalize: out = (gather-sum m2h) * nd + b2 ----------
// HALF-WARP per node: 16 lanes x 8B (uint2 of half2) covers the 128B fp16 row.
__global__ void __launch_bounds__(256)
k_agg2(float* __restrict__ out, const float* __restrict__ b2) {
    int tid = blockIdx.x * 256 + threadIdx.x;
    int n = tid >> 4;
    if (n >= N_NODES) return;
    int l = tid & 15;
    int s0 = g_rowptr[n];
    int e1 = g_rowptr[n + 1];
    float4 acc = make_float4(0.f, 0.f, 0.f, 0.f);
    int e = s0;
    for (; e + 3 < e1; e += 4) {
        int sa = g_esrc[e];
        int sb = g_esrc[e + 1];
        int sc = g_esrc[e + 2];
        int sd = g_esrc[e + 3];
        uint2 ua = *(const uint2*)(g_m2h + (size_t)sa * OUT_F + 4 * l);
        uint2 ub = *(const uint2*)(g_m2h + (size_t)sb * OUT_F + 4 * l);
        uint2 uc = *(const uint2*)(g_m2h + (size_t)sc * OUT_F + 4 * l);
        uint2 ud = *(const uint2*)(g_m2h + (size_t)sd * OUT_F + 4 * l);
        float2 a0 = __half22float2(*(__half2*)&ua.x), a1 = __half22float2(*(__half2*)&ua.y);
        float2 b0 = __half22float2(*(__half2*)&ub.x), b1 = __half22float2(*(__half2*)&ub.y);
        float2 c0 = __half22float2(*(__half2*)&uc.x), c1 = __half22float2(*(__half2*)&uc.y);
        float2 d0 = __half22float2(*(__half2*)&ud.x), d1 = __half22float2(*(__half2*)&ud.y);
        acc.x += (a0.x + b0.x) + (c0.x + d0.x);
        acc.y += (a0.y + b0.y) + (c0.y + d0.y);
        acc.z += (a1.x + b1.x) + (c1.x + d1.x);
        acc.w += (a1.y + b1.y) + (c1.y + d1.y);
    }
    for (; e < e1; e++) {
        int sa = g_esrc[e];
        uint2 ua = *(const uint2*)(g_m2h + (size_t)sa * OUT_F + 4 * l);
        float2 a0 = __half22float2(*(__half2*)&ua.x), a1 = __half22float2(*(__half2*)&ua.y);
        acc.x += a0.x; acc.y += a0.y; acc.z += a1.x; acc.w += a1.y;
    }
    float nd = g_nd[n];
    float4 bv = ((const float4*)b2)[l];
    float4 r;
    r.x = acc.x * nd + bv.x;
    r.y = acc.y * nd + bv.y;
    r.z = acc.z * nd + bv.z;
    r.w = acc.w * nd + bv.w;
    ((float4*)(out + (size_t)n * OUT_F))[l] = r;
}

// ---------------- launch -----------------------------------------------------
extern "C" void kernel_launch(void* const* d_in, const int* in_sizes, int n_in,
                              void* d_out, int out_size) {
    // Identify inputs by element count (robust to any metadata ordering).
    const float *x = 0, *W1 = 0, *b1 = 0, *W2 = 0, *b2 = 0;
    const void *srcp = 0, *dstp = 0;
    for (int i = 0; i < n_in; i++) {
        switch (in_sizes[i]) {
            case N_NODES * IN_F: x  = (const float*)d_in[i]; break;   // 12,800,000
            case IN_F * HID:     W1 = (const float*)d_in[i]; break;   // 32,768
            case HID * OUT_F:    W2 = (const float*)d_in[i]; break;   // 8,192
            case HID:            b1 = (const float*)d_in[i]; break;   // 128
            case OUT_F:          b2 = (const float*)d_in[i]; break;   // 64
            case N_EDGES:                                              // 800,000 (x2)
                if (!srcp) srcp = d_in[i]; else dstp = d_in[i];
                break;
            default: break;
        }
    }
    float* out = (float*)d_out;

    // One-time side-stream + events (host objects only; created outside capture
    // on the harness's eager correctness call, reused during capture/replay).
    static cudaStream_t s2 = 0;
    static cudaEvent_t evFork = 0, evJoin = 0;
    if (!s2) {
        cudaStreamCreateWithFlags(&s2, cudaStreamNonBlocking);
        cudaEventCreateWithFlags(&evFork, cudaEventDisableTiming);
        cudaEventCreateWithFlags(&evJoin, cudaEventDisableTiming);
    }

    // Fork: gemm1 (x @ W1, no CSR dependency) overlaps the whole CSR build.
    cudaEventRecord(evFork, 0);
    cudaStreamWaitEvent(s2, evFork, 0);
    k_gemm1<<<(N_NODES + 127) / 128, 256, 0, s2>>>(x, W1);
    cudaEventRecord(evJoin, s2);

    // Main stream: CSR build chain.
    k_initdetect<<<(N_NODES + 255) / 256, 256>>>((const int*)srcp, (const int*)dstp);
    k_cvtdeg<<<(N_EDGES + 255) / 256, 256>>>(srcp, dstp);
    k_scan1<<<SCAN_NBLK, SCAN_B>>>();
    k_scan3<<<SCAN_NBLK, SCAN_B>>>();
    k_fill<<<(N_EDGES + 255) / 256, 256>>>();

    // Join: agg1 needs both m1 (s2) and the CSR (main).
    cudaStreamWaitEvent(0, evJoin, 0);
    k_agg1<<<(N_NODES * 32) / 256, 256>>>();
    k_gemm2<<<(N_NODES + 127) / 128, 256>>>(b1, W2);
    k_agg2<<<(N_NODES * 16 + 255) / 256, 256>>>(out, b2);
}